// round 5
// baseline (speedup 1.0000x reference)
#include <cuda_runtime.h>
#include <cuda_fp16.h>
#include <math.h>
#include <stdint.h>

// ---------------- problem constants ----------------
#define NB 16
#define NC 128
#define HW 4096           // 64*64
#define CHW (NC*HW)       // 524288
#define AUXC 277
#define AUXK 288          // padded K for embed GEMMs

// ---------------- epilogue modes ----------------
#define EP_BIAS  0
#define EP_ADN   1
#define EP_NONE  2
#define EP_TANH  3
#define EP_GELU  4
#define EP_FINAL 5
#define EP_QKV   6
#define EP_PV1   7
#define EP_PV2   8

// ---------------- weight pack offsets (halfs) ----------------
#define WO_Q    0
#define WO_K    16384
#define WO_V    32768
#define WO_E1   49152     // [128][288] padded
#define WO_S1   86016
#define WO_B1   102400    // [128][256]
#define WO_E2   135168
#define WO_S2W  172032
#define WO_B2   188416
#define WO_SC   221184    // [128][1152]
#define WO_BI1  368640
#define WO_BI2  516096
#define W_TOTAL 663552

// ---------------- scratch ----------------
__device__ __align__(256) half g_wh  [W_TOTAL];
__device__ __align__(256) half g_auxh[NB*AUXK*HW];
__device__ __align__(256) half g_xh  [NB*CHW];
__device__ __align__(256) half g_ah  [NB*CHW];
__device__ __align__(256) half g_t0h [NB*CHW];
__device__ __align__(256) half g_midh[NB*CHW];
__device__ __align__(256) half g_oh  [NB*CHW];
__device__ __align__(256) half g_tmph[NB*CHW];
__device__ __align__(256) half g_qp1h[NB*1024*256];
__device__ __align__(256) half g_kp1h[NB*1024*256];
__device__ __align__(256) half g_vp1h[NB*1024*256];
__device__ __align__(256) half g_qp2h[NB*256*1024];
__device__ __align__(256) half g_kp2h[NB*256*1024];
__device__ __align__(256) half g_vp2h[NB*256*1024];
__device__ __align__(256) half g_s1h [NB*1024L*1024];
__device__ __align__(256) half g_s2h [NB*256*256];
__device__ __align__(256) half g_im  [NB*1152L*4096];

__device__ float g_t0   [NB*CHW];
__device__ float g_gamma[NB*CHW];
__device__ float g_betaS[NB*CHW];
__device__ float g_mid  [NB*CHW];
__device__ float g_gf   [NB*CHW];
__device__ float g_s1   [NB*1024L*1024];
__device__ float g_s2   [NB*256*256];
__device__ float g_stats[NB*2];
__device__ float g_part [NB*64*2];

// ---------------- smem geometry ----------------
#define STAGES 4
#define STAGE_BYTES 20480          // A: 128*80B = 10240 ; B region: 10240
#define SMEM_BYTES (STAGES*STAGE_BYTES)   // 81920
#define A_ROWB 80                  // 40 halfs (32 + 8 pad)
#define B_ROWB 272                 // 136 halfs (128 + 8 pad) for k-major B

// ---------------- asm helpers ----------------
__device__ __forceinline__ void cp16(uint32_t dst, const void* src) {
    asm volatile("cp.async.cg.shared.global [%0], [%1], 16;" :: "r"(dst), "l"(src));
}
__device__ __forceinline__ void cp_commit() {
    asm volatile("cp.async.commit_group;");
}
__device__ __forceinline__ void cp_wait2() {
    asm volatile("cp.async.wait_group 2;");
}
__device__ __forceinline__ void ldsm_x4(uint32_t* r, uint32_t addr) {
    asm volatile("ldmatrix.sync.aligned.m8n8.x4.shared.b16 {%0,%1,%2,%3}, [%4];"
                 : "=r"(r[0]), "=r"(r[1]), "=r"(r[2]), "=r"(r[3]) : "r"(addr));
}
__device__ __forceinline__ void ldsm_x4t(uint32_t* r, uint32_t addr) {
    asm volatile("ldmatrix.sync.aligned.m8n8.x4.trans.shared.b16 {%0,%1,%2,%3}, [%4];"
                 : "=r"(r[0]), "=r"(r[1]), "=r"(r[2]), "=r"(r[3]) : "r"(addr));
}
__device__ __forceinline__ void mma_f16(float* c,
                                        uint32_t a0, uint32_t a1, uint32_t a2, uint32_t a3,
                                        uint32_t b0, uint32_t b1) {
    asm volatile(
        "mma.sync.aligned.m16n8k16.row.col.f32.f16.f16.f32 "
        "{%0,%1,%2,%3}, {%4,%5,%6,%7}, {%8,%9}, {%0,%1,%2,%3};"
        : "+f"(c[0]), "+f"(c[1]), "+f"(c[2]), "+f"(c[3])
        : "r"(a0), "r"(a1), "r"(a2), "r"(a3), "r"(b0), "r"(b1));
}

// ================= weight conversion (fp32 -> packed fp16) =================
__global__ void __launch_bounds__(256)
wconv_kernel(const float* qw, const float* kw, const float* vw,
             const float* e1, const float* s1, const float* b1,
             const float* e2, const float* s2, const float* b2,
             const float* sc, const float* bi1, const float* bi2) {
    int i = blockIdx.x * 256 + threadIdx.x;
    if (i >= W_TOTAL) return;
    float v;
    if (i < WO_E1) {
        int seg = i / 16384, j = i % 16384;
        v = (seg == 0 ? qw : seg == 1 ? kw : vw)[j];
    } else if (i < WO_S1) {
        int j = i - WO_E1, r = j / AUXK, c = j % AUXK;
        v = (c < AUXC) ? e1[r * AUXC + c] : 0.f;
    } else if (i < WO_B1)  v = s1[i - WO_S1];
    else if (i < WO_E2)    v = b1[i - WO_B1];
    else if (i < WO_S2W) {
        int j = i - WO_E2, r = j / AUXK, c = j % AUXK;
        v = (c < AUXC) ? e2[r * AUXC + c] : 0.f;
    } else if (i < WO_B2)  v = s2[i - WO_S2W];
    else if (i < WO_SC)    v = b2[i - WO_B2];
    else if (i < WO_BI1)   v = sc[i - WO_SC];
    else if (i < WO_BI2)   v = bi1[i - WO_BI1];
    else                   v = bi2[i - WO_BI2];
    g_wh[i] = __float2half_rn(v);
}

// ================= concat aux (half, padded to 288 rows) =================
__global__ void __launch_bounds__(256)
concat_aux_kernel(const float* __restrict__ edge, const float* __restrict__ seg,
                  const float* __restrict__ pe,   const float* __restrict__ ps) {
    long i = (long)blockIdx.x * 256 + threadIdx.x;
    long total = (long)NB * AUXK * HW;
    if (i >= total) return;
    int p = (int)(i % HW);
    long t = i / HW;
    int c = (int)(t % AUXK);
    int b = (int)(t / AUXK);
    float v = 0.f;
    if (c < 128)       v = edge[((long)b*128 + c)      * HW + p];
    else if (c < 256)  v = seg [((long)b*128 + (c-128))* HW + p];
    else if (c == 256) v = pe  [(long)b * HW + p];
    else if (c < AUXC) v = ps  [((long)b*20 + (c-257)) * HW + p];
    g_auxh[i] = __float2half_rn(v);
}

// ================= fp32 -> fp16 convert =================
__global__ void __launch_bounds__(256)
cvt_f2h_kernel(const float* __restrict__ src, half* __restrict__ dst, long n) {
    long i = (long)blockIdx.x * 256 + threadIdx.x;
    if (i < n) dst[i] = __float2half_rn(src[i]);
}

// ================= im2col (half): dst[b][k][p], k = c*9 + ky*3 + kx =================
__global__ void __launch_bounds__(256)
im2col_kernel(const half* __restrict__ X, half* __restrict__ dst, int dil) {
    long i = (long)blockIdx.x * 256 + threadIdx.x;
    long total = (long)NB * 1152 * 512;      // 8 px per thread
    if (i >= total) return;
    int segp = (int)(i & 511);
    long t = i >> 9;
    int k = (int)(t % 1152);
    int b = (int)(t / 1152);
    int c  = k / 9;
    int t9 = k - c * 9;
    int dy = (t9 / 3 - 1) * dil;
    int dx = (t9 % 3 - 1) * dil;
    int p0 = segp * 8;
    int h = p0 >> 6, w0 = p0 & 63;
    int gh = h + dy;
    half vals[8];
    if ((unsigned)gh < 64u) {
        const half* row = X + ((long)(b * 128 + c) * 64 + gh) * 64;
#pragma unroll
        for (int j = 0; j < 8; j++) {
            int w = w0 + j + dx;
            vals[j] = ((unsigned)w < 64u) ? row[w] : __float2half_rn(0.f);
        }
    } else {
#pragma unroll
        for (int j = 0; j < 8; j++) vals[j] = __float2half_rn(0.f);
    }
    *(uint4*)(dst + ((long)b * 1152 + k) * 4096 + p0) = *(uint4*)vals;
}

// ================= fp16 GEMM, cp.async 4-stage pipeline =================
// TRANSB=0: C[m,n] = A[m,k] * B[k,n]   (B row-major [K][N])
// TRANSB=1: C[m,n] = A[m,k] * B[n,k]   (B row-major [N][K])
// CTA tile 128x128, 8 warps of 64x32, Kt=32. K must be a multiple of 32, >= 128.
template<bool TRANSB>
__global__ void __launch_bounds__(256)
hgemm(const half* __restrict__ A, int lda, long sA_,
      const half* __restrict__ Bm, int ldb, long sB_,
      float* __restrict__ Cf, half* __restrict__ Ch, long sC_,
      int N, int K, int mode, float scale,
      const float* __restrict__ bias,
      const float* __restrict__ t0,
      const float* __restrict__ gamma,
      const float* __restrict__ betaS,
      const float* __restrict__ stats,
      const float* __restrict__ mid,
      const float* __restrict__ gf,
      half* __restrict__ dst1,
      half* __restrict__ dst2)
{
    extern __shared__ half sm[];
    int bb = blockIdx.z;
    int n0 = blockIdx.x * 128;
    int m0 = blockIdx.y * 128;
    const half* Ap = A  + (long)bb * sA_;
    const half* Bp = Bm + (long)bb * sB_;

    int tid  = threadIdx.x;
    int lane = tid & 31;
    int warp = tid >> 5;
    int wm = (warp >> 2) * 64;
    int wn = (warp & 3) * 32;

    uint32_t sb0 = (uint32_t)__cvta_generic_to_shared(sm);
    int nkt = K >> 5;

    float acc[4][4][4] = {};

    auto load_tile = [&](int it) {
        uint32_t sa  = sb0 + (uint32_t)((it & (STAGES-1)) * STAGE_BYTES);
        uint32_t sbB = sa + 10240;
        int kt = it * 32;
#pragma unroll
        for (int i = 0; i < 2; i++) {
            int ch = tid + i * 256;
            {   // A: 128 rows x 64B
                int row = ch >> 2, c4 = ch & 3;
                cp16(sa + row * A_ROWB + c4 * 16,
                     Ap + (long)(m0 + row) * lda + kt + c4 * 8);
            }
            if (TRANSB) {   // B: 128 n-rows x 64B
                int row = ch >> 2, c4 = ch & 3;
                cp16(sbB + row * A_ROWB + c4 * 16,
                     Bp + (long)(n0 + row) * ldb + kt + c4 * 8);
            } else {        // B: 32 k-rows x 256B
                int row = ch >> 4, c16 = ch & 15;
                cp16(sbB + row * B_ROWB + c16 * 16,
                     Bp + (long)(kt + row) * ldb + n0 + c16 * 8);
            }
        }
    };

    // prologue: STAGES-1 tiles in flight
#pragma unroll
    for (int s = 0; s < STAGES - 1; s++) {
        if (s < nkt) load_tile(s);
        cp_commit();
    }

    for (int it = 0; it < nkt; it++) {
        cp_wait2();
        __syncthreads();

        int nx = it + STAGES - 1;
        if (nx < nkt) load_tile(nx);
        cp_commit();

        uint32_t sa  = sb0 + (uint32_t)((it & (STAGES-1)) * STAGE_BYTES);
        uint32_t sbB = sa + 10240;
        uint32_t abase = sa + (uint32_t)(wm + (lane & 15)) * A_ROWB + ((lane >> 4) * 16);

#pragma unroll
        for (int ks = 0; ks < 2; ks++) {
            uint32_t af[4][4];
#pragma unroll
            for (int mt = 0; mt < 4; mt++)
                ldsm_x4(af[mt], abase + mt * 16 * A_ROWB + ks * 32);

            uint32_t bf[2][4];
            if (TRANSB) {
                uint32_t bbase = sbB + (uint32_t)(wn + (lane & 15)) * A_ROWB + ((lane >> 4) * 16);
#pragma unroll
                for (int ntp = 0; ntp < 2; ntp++)
                    ldsm_x4(bf[ntp], bbase + ntp * 16 * A_ROWB + ks * 32);
            } else {
                uint32_t bbase = sbB + (uint32_t)(ks * 16 + (lane & 15)) * B_ROWB
                               + (uint32_t)(wn + (lane >> 4) * 8) * 2;
#pragma unroll
                for (int ntp = 0; ntp < 2; ntp++)
                    ldsm_x4t(bf[ntp], bbase + ntp * 32);
            }

#pragma unroll
            for (int mt = 0; mt < 4; mt++) {
#pragma unroll
                for (int nt = 0; nt < 4; nt++) {
                    int ntp = nt >> 1, par = nt & 1;
                    uint32_t b0 = TRANSB ? bf[ntp][par]     : bf[ntp][par * 2];
                    uint32_t b1 = TRANSB ? bf[ntp][par + 2] : bf[ntp][par * 2 + 1];
                    mma_f16(acc[mt][nt], af[mt][0], af[mt][1], af[mt][2], af[mt][3], b0, b1);
                }
            }
        }
        __syncthreads();
    }

    // ---- epilogue ----
    int r  = lane >> 2;
    int cg = lane & 3;
    float mu = 0.f, rs = 0.f;
    if (mode == EP_ADN || mode == EP_QKV) { mu = stats[2 * bb]; rs = stats[2 * bb + 1]; }
    long bbC = (long)bb * sC_;
    float* Cfp = Cf ? Cf + bbC : nullptr;
    half*  Chp = Ch ? Ch + bbC : nullptr;

    auto emit = [&](float v, int m, int n) {
        long li = (long)m * N + n;
        long gidx = bbC + li;
        if (mode == EP_QKV) {
            float val = (t0[gidx] - mu) * rs * gamma[gidx] + v + betaS[gidx];
            int h = n >> 6, w = n & 63;
            if (m < 64) {
                int nn = (h >> 1) * 32 + (w >> 1);
                int d  = m * 4 + (h & 1) * 2 + (w & 1);
                dst1[(long)bb * (1024L*256) + (long)nn * 256 + d] = __float2half_rn(val);
            } else {
                int nn = (h >> 2) * 16 + (w >> 2);
                int d  = (m - 64) * 16 + (h & 3) * 4 + (w & 3);
                dst2[(long)bb * (256L*1024) + (long)nn * 1024 + d] = __float2half_rn(val);
            }
            return;
        }
        long tgt = li;
        float res;
        if (mode == EP_BIAS) {
            res = v + bias[m];
        } else if (mode == EP_ADN) {
            res = (t0[gidx] - mu) * rs * gamma[gidx] + v + betaS[gidx];
        } else if (mode == EP_NONE) {
            res = v * scale;
        } else if (mode == EP_TANH) {
            res = tanhf(v + bias[m]);
        } else if (mode == EP_GELU) {
            float u = v + bias[m];
            res = 0.5f * u * (1.f + erff(u * 0.70710678118654752f));
        } else if (mode == EP_FINAL) {
            res = mid[gidx] * gf[gidx] + v + bias[m];
        } else if (mode == EP_PV1) {
            int c  = n >> 2;
            int py = (n >> 1) & 1, px = n & 1;
            int h = (m >> 5) * 2 + py, w = (m & 31) * 2 + px;
            tgt = (long)c * HW + h * 64 + w;
            res = t0[bbC + tgt] + v;
        } else { // EP_PV2
            int c  = 64 + (n >> 4);
            int py = (n >> 2) & 3, px = n & 3;
            int h = (m >> 4) * 4 + py, w = (m & 15) * 4 + px;
            tgt = (long)c * HW + h * 64 + w;
            res = t0[bbC + tgt] + v;
        }
        if (Cfp) Cfp[tgt] = res;
        if (Chp) Chp[tgt] = __float2half_rn(res);
    };

#pragma unroll
    for (int mt = 0; mt < 4; mt++) {
#pragma unroll
        for (int nt = 0; nt < 4; nt++) {
            int m1 = m0 + wm + mt * 16 + r;
            int m2 = m1 + 8;
            int nn = n0 + wn + nt * 8 + cg * 2;
            emit(acc[mt][nt][0], m1, nn);
            emit(acc[mt][nt][1], m1, nn + 1);
            emit(acc[mt][nt][2], m2, nn);
            emit(acc[mt][nt][3], m2, nn + 1);
        }
    }
}

// ================= LayerNorm stats =================
__global__ void __launch_bounds__(256)
ln_part_kernel(const float* __restrict__ src) {
    int b = blockIdx.y, ch = blockIdx.x;
    const int CH = CHW / 64;
    const float* p = src + (long)b * CHW + (long)ch * CH;
    int tid = threadIdx.x;
    float s = 0.f, q = 0.f;
    for (int i = tid; i < CH; i += 256) { float v = p[i]; s += v; q += v * v; }
    __shared__ float shs[8], shq[8];
#pragma unroll
    for (int o = 16; o; o >>= 1) {
        s += __shfl_xor_sync(0xffffffffu, s, o);
        q += __shfl_xor_sync(0xffffffffu, q, o);
    }
    if ((tid & 31) == 0) { shs[tid >> 5] = s; shq[tid >> 5] = q; }
    __syncthreads();
    if (tid < 8) {
        s = shs[tid]; q = shq[tid];
#pragma unroll
        for (int o = 4; o; o >>= 1) {
            s += __shfl_xor_sync(0xffu, s, o);
            q += __shfl_xor_sync(0xffu, q, o);
        }
        if (tid == 0) {
            g_part[(b * 64 + ch) * 2 + 0] = s;
            g_part[(b * 64 + ch) * 2 + 1] = q;
        }
    }
}

__global__ void ln_final_kernel() {
    int b = blockIdx.x;
    int tid = threadIdx.x;
    float s = 0.f, q = 0.f;
    for (int i = tid; i < 64; i += 32) {
        s += g_part[(b * 64 + i) * 2 + 0];
        q += g_part[(b * 64 + i) * 2 + 1];
    }
#pragma unroll
    for (int o = 16; o; o >>= 1) {
        s += __shfl_xor_sync(0xffffffffu, s, o);
        q += __shfl_xor_sync(0xffffffffu, q, o);
    }
    if (tid == 0) {
        float mu = s / (float)CHW;
        float var = q / (float)CHW - mu * mu;
        g_stats[2 * b]     = mu;
        g_stats[2 * b + 1] = rsqrtf(var + 1e-5f);
    }
}

// ================= fused softmax (fp32 in, half out) =================
__global__ void __launch_bounds__(256)
softmax_h_kernel(const float* __restrict__ S, half* __restrict__ P, int L, int VPT) {
    long row = blockIdx.x;
    const float* p = S + row * (long)L;
    half* o = P + row * (long)L;
    int tid = threadIdx.x;
    __shared__ float sh[8];
    float v[4];
    for (int i = 0; i < VPT; i++) v[i] = p[tid + i * 256];

    float mx = -3.4e38f;
    for (int i = 0; i < VPT; i++) mx = fmaxf(mx, v[i]);
#pragma unroll
    for (int og = 16; og; og >>= 1) mx = fmaxf(mx, __shfl_xor_sync(0xffffffffu, mx, og));
    if ((tid & 31) == 0) sh[tid >> 5] = mx;
    __syncthreads();
    if (tid < 8) {
        float t = sh[tid];
#pragma unroll
        for (int og = 4; og; og >>= 1) t = fmaxf(t, __shfl_xor_sync(0xffu, t, og));
        if (tid == 0) sh[0] = t;
    }
    __syncthreads();
    mx = sh[0];
    __syncthreads();

    float s = 0.f;
    for (int i = 0; i < VPT; i++) { v[i] = __expf(v[i] - mx); s += v[i]; }
#pragma unroll
    for (int og = 16; og; og >>= 1) s += __shfl_xor_sync(0xffffffffu, s, og);
    if ((tid & 31) == 0) sh[tid >> 5] = s;
    __syncthreads();
    if (tid < 8) {
        float t = sh[tid];
#pragma unroll
        for (int og = 4; og; og >>= 1) t += __shfl_xor_sync(0xffu, t, og);
        if (tid == 0) sh[0] = t;
    }
    __syncthreads();
    float inv = 1.f / sh[0];
    for (int i = 0; i < VPT; i++) o[tid + i * 256] = __float2half_rn(v[i] * inv);
}

// ================= host side =================
struct Bufs {
    half *wh, *auxh, *xh, *ah, *t0h, *midh, *oh, *tmph;
    half *qp1, *kp1, *vp1, *qp2, *kp2, *vp2, *s1h, *s2h, *im;
    float *t0, *gamma, *betaS, *mid, *gf, *s1, *s2, *stats;
};

static void launch_hgemm(bool transb,
                         const half* A, int lda, long sA,
                         const half* B, int ldb, long sB,
                         float* Cf, half* Ch, long sC,
                         int M, int N, int K, int mode, float scale,
                         const float* bias = nullptr, const float* t0 = nullptr,
                         const float* gamma = nullptr, const float* betaS = nullptr,
                         const float* stats = nullptr,
                         const float* mid = nullptr, const float* gf = nullptr,
                         half* dst1 = nullptr, half* dst2 = nullptr) {
    dim3 grid(N / 128, M / 128, NB);
    if (transb)
        hgemm<true><<<grid, 256, SMEM_BYTES>>>(A, lda, sA, B, ldb, sB, Cf, Ch, sC, N, K,
                                               mode, scale, bias, t0, gamma, betaS, stats,
                                               mid, gf, dst1, dst2);
    else
        hgemm<false><<<grid, 256, SMEM_BYTES>>>(A, lda, sA, B, ldb, sB, Cf, Ch, sC, N, K,
                                                mode, scale, bias, t0, gamma, betaS, stats,
                                                mid, gf, dst1, dst2);
}

extern "C" void kernel_launch(void* const* d_in, const int* in_sizes, int n_in,
                              void* d_out, int out_size) {
    const float* x    = (const float*)d_in[0];
    const float* edge = (const float*)d_in[1];
    const float* seg  = (const float*)d_in[2];
    const float* pe   = (const float*)d_in[3];
    const float* ps   = (const float*)d_in[4];
    const float* q_w  = (const float*)d_in[5];
    const float* q_b  = (const float*)d_in[6];
    const float* k_w  = (const float*)d_in[7];
    const float* k_b  = (const float*)d_in[8];
    const float* v_w  = (const float*)d_in[9];
    const float* v_b  = (const float*)d_in[10];
    const float* d1_embed_w = (const float*)d_in[11];
    const float* d1_embed_b = (const float*)d_in[12];
    const float* d1_scale_w = (const float*)d_in[13];
    const float* d1_scale_b = (const float*)d_in[14];
    const float* d1_bias_w  = (const float*)d_in[15];
    const float* d1_bias_b  = (const float*)d_in[16];
    const float* d2_embed_w = (const float*)d_in[17];
    const float* d2_embed_b = (const float*)d_in[18];
    const float* d2_scale_w = (const float*)d_in[19];
    const float* d2_scale_b = (const float*)d_in[20];
    const float* d2_bias_w  = (const float*)d_in[21];
    const float* d2_bias_b  = (const float*)d_in[22];
    const float* sc_w  = (const float*)d_in[23];
    const float* sc_b  = (const float*)d_in[24];
    const float* bi1_w = (const float*)d_in[25];
    const float* bi1_b = (const float*)d_in[26];
    const float* bi2_w = (const float*)d_in[27];
    const float* bi2_b = (const float*)d_in[28];
    float* out = (float*)d_out;

    cudaFuncSetAttribute(hgemm<false>, cudaFuncAttributeMaxDynamicSharedMemorySize, SMEM_BYTES);
    cudaFuncSetAttribute(hgemm<true>,  cudaFuncAttributeMaxDynamicSharedMemorySize, SMEM_BYTES);

    Bufs bf;
    cudaGetSymbolAddress((void**)&bf.wh,    g_wh);
    cudaGetSymbolAddress((void**)&bf.auxh,  g_auxh);
    cudaGetSymbolAddress((void**)&bf.xh,    g_xh);
    cudaGetSymbolAddress((void**)&bf.ah,    g_ah);
    cudaGetSymbolAddress((void**)&bf.t0h,   g_t0h);
    cudaGetSymbolAddress((void**)&bf.midh,  g_midh);
    cudaGetSymbolAddress((void**)&bf.oh,    g_oh);
    cudaGetSymbolAddress((void**)&bf.tmph,  g_tmph);
    cudaGetSymbolAddress((void**)&bf.qp1,   g_qp1h);
    cudaGetSymbolAddress((void**)&bf.kp1,   g_kp1h);
    cudaGetSymbolAddress((void**)&bf.vp1,   g_vp1h);
    cudaGetSymbolAddress((void**)&bf.qp2,   g_qp2h);
    cudaGetSymbolAddress((void**)&bf.kp2,   g_kp2h);
    cudaGetSymbolAddress((void**)&bf.vp2,   g_vp2h);
    cudaGetSymbolAddress((void**)&bf.s1h,   g_s1h);
    cudaGetSymbolAddress((void**)&bf.s2h,   g_s2h);
    cudaGetSymbolAddress((void**)&bf.im,    g_im);
    cudaGetSymbolAddress((void**)&bf.t0,    g_t0);
    cudaGetSymbolAddress((void**)&bf.gamma, g_gamma);
    cudaGetSymbolAddress((void**)&bf.betaS, g_betaS);
    cudaGetSymbolAddress((void**)&bf.mid,   g_mid);
    cudaGetSymbolAddress((void**)&bf.gf,    g_gf);
    cudaGetSymbolAddress((void**)&bf.s1,    g_s1);
    cudaGetSymbolAddress((void**)&bf.s2,    g_s2);
    cudaGetSymbolAddress((void**)&bf.stats, g_stats);

    // 0. conversions
    wconv_kernel<<<(W_TOTAL + 255) / 256, 256>>>(q_w, k_w, v_w,
                                                 d1_embed_w, d1_scale_w, d1_bias_w,
                                                 d2_embed_w, d2_scale_w, d2_bias_w,
                                                 sc_w, bi1_w, bi2_w);
    cvt_f2h_kernel<<<(int)(((long)NB * CHW + 255) / 256), 256>>>(x, bf.xh, (long)NB * CHW);
    {
        long total = (long)NB * AUXK * HW;
        concat_aux_kernel<<<(int)((total + 255) / 256), 256>>>(edge, seg, pe, ps);
    }

    // 1. ADN-1 shared pieces
    launch_hgemm(false, bf.wh + WO_E1, AUXK, 0, bf.auxh, HW, (long)AUXK * HW,
                 nullptr, bf.ah, CHW, NC, HW, AUXK, EP_BIAS, 1.f, d1_embed_b);
    launch_hgemm(false, bf.wh + WO_S1, NC, 0, bf.ah, HW, CHW,
                 bf.gamma, nullptr, CHW, NC, HW, NC, EP_BIAS, 1.f, d1_scale_b);
    launch_hgemm(false, bf.wh + WO_B1 + NC, 2 * NC, 0, bf.ah, HW, CHW,
                 bf.betaS, nullptr, CHW, NC, HW, NC, EP_BIAS, 1.f, d1_bias_b);

    // 2. q/k/v: conv1x1 -> LN -> ADN (patched half outputs)
    const long WOFF[3] = { WO_Q, WO_K, WO_V };
    const float* tb[3] = { q_b, k_b, v_b };
    half* p1[3] = { bf.qp1, bf.kp1, bf.vp1 };
    half* p2[3] = { bf.qp2, bf.kp2, bf.vp2 };
    for (int t = 0; t < 3; t++) {
        launch_hgemm(false, bf.wh + WOFF[t], NC, 0, bf.xh, HW, CHW,
                     bf.t0, bf.t0h, CHW, NC, HW, NC, EP_BIAS, 1.f, tb[t]);
        ln_part_kernel<<<dim3(64, NB), 256>>>(bf.t0);
        ln_final_kernel<<<NB, 32>>>();
        launch_hgemm(false, bf.wh + WO_B1, 2 * NC, 0, bf.t0h, HW, CHW,
                     nullptr, nullptr, CHW, NC, HW, NC, EP_QKV, 1.f,
                     nullptr, bf.t0, bf.gamma, bf.betaS, bf.stats,
                     nullptr, nullptr, p1[t], p2[t]);
    }

    // 3. attention scale 1: 1024 tokens, d=256
    launch_hgemm(true, bf.qp1, 256, 1024L * 256, bf.kp1, 256, 1024L * 256,
                 bf.s1, nullptr, 1024L * 1024, 1024, 1024, 256, EP_NONE, 0.0625f);
    softmax_h_kernel<<<NB * 1024, 256>>>(bf.s1, bf.s1h, 1024, 4);
    launch_hgemm(false, bf.s1h, 1024, 1024L * 1024, bf.vp1, 256, 1024L * 256,
                 bf.mid, bf.midh, CHW, 1024, 256, 1024, EP_PV1, 1.f,
                 nullptr, x);

    // 4. attention scale 2: 256 tokens, d=1024
    launch_hgemm(true, bf.qp2, 1024, 256L * 1024, bf.kp2, 1024, 256L * 1024,
                 bf.s2, nullptr, 256L * 256, 256, 256, 1024, EP_NONE, 0.03125f);
    softmax_h_kernel<<<NB * 256, 256>>>(bf.s2, bf.s2h, 256, 1);
    launch_hgemm(false, bf.s2h, 256, 256L * 256, bf.vp2, 1024, 256L * 1024,
                 bf.mid, bf.midh, CHW, 256, 1024, 256, EP_PV2, 1.f,
                 nullptr, x);

    // 5. ADN-2
    launch_hgemm(false, bf.wh + WO_E2, AUXK, 0, bf.auxh, HW, (long)AUXK * HW,
                 nullptr, bf.ah, CHW, NC, HW, AUXK, EP_BIAS, 1.f, d2_embed_b);
    launch_hgemm(false, bf.wh + WO_S2W, NC, 0, bf.ah, HW, CHW,
                 bf.gamma, nullptr, CHW, NC, HW, NC, EP_BIAS, 1.f, d2_scale_b);
    launch_hgemm(false, bf.wh + WO_B2 + NC, 2 * NC, 0, bf.ah, HW, CHW,
                 bf.betaS, nullptr, CHW, NC, HW, NC, EP_BIAS, 1.f, d2_bias_b);
    ln_part_kernel<<<dim3(64, NB), 256>>>(bf.mid);
    ln_final_kernel<<<NB, 32>>>();
    launch_hgemm(false, bf.wh + WO_B2, 2 * NC, 0, bf.midh, HW, CHW,
                 nullptr, bf.oh, CHW, NC, HW, NC, EP_ADN, 1.f,
                 nullptr, bf.mid, bf.gamma, bf.betaS, bf.stats);

    // 6. conv3x3 chain via im2col + GEMM
    const int IM_BLOCKS = (int)(((long)NB * 1152 * 512 + 255) / 256);
    im2col_kernel<<<IM_BLOCKS, 256>>>(bf.oh, bf.im, 1);
    launch_hgemm(false, bf.wh + WO_SC, 1152, 0, bf.im, HW, 1152L * HW,
                 bf.gf, nullptr, CHW, NC, HW, 1152, EP_TANH, 1.f, sc_b);

    im2col_kernel<<<IM_BLOCKS, 256>>>(bf.oh, bf.im, 2);
    launch_hgemm(false, bf.wh + WO_BI1, 1152, 0, bf.im, HW, 1152L * HW,
                 nullptr, bf.tmph, CHW, NC, HW, 1152, EP_GELU, 1.f, bi1_b);

    im2col_kernel<<<IM_BLOCKS, 256>>>(bf.tmph, bf.im, 1);
    launch_hgemm(false, bf.wh + WO_BI2, 1152, 0, bf.im, HW, 1152L * HW,
                 out, nullptr, CHW, NC, HW, 1152, EP_FINAL, 1.f, bi2_b,
                 nullptr, nullptr, nullptr, nullptr, bf.mid, bf.gf);
}

// round 7
// speedup vs baseline: 1.0480x; 1.0480x over previous
#include <cuda_runtime.h>
#include <cuda_fp16.h>
#include <math.h>
#include <stdint.h>

// ---------------- problem constants ----------------
#define NB 16
#define HW 4096
#define CHW (128*HW)          // 524288
#define AUXC 277
#define AUXK 288

// ---------------- weight pack offsets (halfs) ----------------
#define WO_QKV  0             // [384][128]
#define WO_E1   49152         // [128][288]
#define WO_GB1  86016         // [256][128]  rows: scale_w, bias_w[:,128:]
#define WO_B1   118784        // [128][256]  full bias_w (use cols :128 with lda=256)
#define WO_E2   151552
#define WO_GB2  188416
#define WO_B2   221184
#define WO_SC   253952        // [128][1152]
#define WO_BI1  401408
#define WO_BI2  548864
#define W_TOTAL 696320

// ---------------- scratch ----------------
__device__ __align__(256) half  g_wh  [W_TOTAL];
__device__ float g_qkvb[384];
__device__ float g_gbb1[256];
__device__ float g_gbb2[256];
__device__ __align__(256) half  g_auxh[(long)NB*AUXK*HW];
__device__ __align__(256) half  g_xh  [(long)NB*CHW];
__device__ __align__(256) half  g_ah  [(long)NB*CHW];
__device__ __align__(256) half  g_t0h [(long)NB*3*CHW];
__device__ __align__(256) float g_t0f [(long)NB*3*CHW];
__device__ __align__(256) float g_gam [(long)NB*CHW];
__device__ __align__(256) float g_bet [(long)NB*CHW];
__device__ __align__(256) half  g_midh[(long)NB*CHW];
__device__ __align__(256) float g_midf[(long)NB*CHW];
__device__ __align__(256) half  g_oh  [(long)NB*CHW];
__device__ __align__(256) float g_gf  [(long)NB*CHW];
__device__ __align__(256) half  g_tmph[(long)NB*CHW];
__device__ __align__(256) half  g_qp1 [NB*1024L*256];
__device__ __align__(256) half  g_kp1 [NB*1024L*256];
__device__ __align__(256) half  g_vp1 [NB*1024L*256];
__device__ __align__(256) half  g_qp2 [NB*256L*1024];
__device__ __align__(256) half  g_kp2 [NB*256L*1024];
__device__ __align__(256) half  g_vp2 [NB*256L*1024];
__device__ __align__(256) float g_s1  [NB*1024L*1024];
__device__ __align__(256) half  g_s1h [NB*1024L*1024];
__device__ __align__(256) float g_s2  [NB*256L*256];
__device__ __align__(256) half  g_s2h [NB*256L*256];
__device__ float g_stats[96];
__device__ float g_part [48*64*2];

// ---------------- epilogue modes ----------------
#define EP_LIN   0
#define EP_GB    1
#define EP_QKV3  2
#define EP_ADN   3
#define EP_SCORE 4
#define EP_PV1   5
#define EP_PV2   6
#define EP_TANH  7
#define EP_GELU  8
#define EP_FINAL 9

// ---------------- smem geometry (halfs) ----------------
#define LDH 40
#define ROWB 80
#define STAGE_BYTES 20480     // A 128*80 + B 128*80
#define STAGE_HALFS 10240

// ---------------- asm helpers ----------------
__device__ __forceinline__ uint32_t smem_u32(const void* p) {
    uint32_t a;
    asm("{ .reg .u64 t; cvta.to.shared.u64 t, %1; cvt.u32.u64 %0, t; }" : "=r"(a) : "l"(p));
    return a;
}
__device__ __forceinline__ void ldsm_x4(uint32_t* r, uint32_t addr) {
    asm volatile("ldmatrix.sync.aligned.m8n8.x4.shared.b16 {%0,%1,%2,%3}, [%4];"
                 : "=r"(r[0]), "=r"(r[1]), "=r"(r[2]), "=r"(r[3]) : "r"(addr));
}
__device__ __forceinline__ void mma_f16(float* c,
                                        uint32_t a0, uint32_t a1, uint32_t a2, uint32_t a3,
                                        uint32_t b0, uint32_t b1) {
    asm volatile(
        "mma.sync.aligned.m16n8k16.row.col.f32.f16.f16.f32 "
        "{%0,%1,%2,%3}, {%4,%5,%6,%7}, {%8,%9}, {%0,%1,%2,%3};"
        : "+f"(c[0]), "+f"(c[1]), "+f"(c[2]), "+f"(c[3])
        : "r"(a0), "r"(a1), "r"(a2), "r"(a3), "r"(b0), "r"(b1));
}

// ---------------- GEMM params ----------------
struct GP {
    const half* A; int lda; long sA;
    const half* B; int ldb; long sB;
    int N; long sC; int nkt;
    int mode; float scale; int dil;
    const float* bias;
    const float* t0f; const float* gamma; const float* betaS; const float* stats;
    const float* xres; const float* midf; const float* gff;
    float* of; float* of2; half* ohh;
    half* d1q; half* d1k; half* d1v;
    half* d2q; half* d2k; half* d2v;
};

// ================= fp16 tensor-core GEMM =================
// TRANSB=0, CONV=0 : C[m,n] = A[m,k] * B[k,n]
// TRANSB=1         : C[m,n] = A[m,k] * B[n,k]
// CONV=1           : B gathered from NCHW-half activations [128][64][64], K=1152
template<bool TRANSB, bool CONV>
__global__ void __launch_bounds__(256)
hgemm6(GP g) {
    __shared__ half sm[2 * STAGE_HALFS];
    int bb = blockIdx.z;
    int n0 = blockIdx.x * 128;
    int m0 = blockIdx.y * 128;
    const half* Ap = g.A + (long)bb * g.sA;
    const half* Bp = g.B + (long)bb * g.sB;

    int tid  = threadIdx.x;
    int lane = tid & 31;
    int warp = tid >> 5;
    int wm = (warp >> 2) * 64;
    int wn = (warp & 3) * 32;

    int arow  = tid >> 1;           // 0..127
    int akseg = (tid & 1) * 16;     // halfs
    int bk    = tid & 31;
    int bn0   = (tid >> 5) * 16;

    uint32_t sbase = smem_u32(sm);
    int rowsel = lane & 15;
    int colsel = (lane >> 4) * 16;

    uint4 ra0, ra1, rb0, rb1;
    half rc[16];
    float acc[4][4][4] = {};
    int nkt = g.nkt;

    for (int it = 0; it <= nkt; it++) {
        // ---- global load tile `it` into registers ----
        if (it < nkt) {
            int kt = it * 32;
            const half* ar = Ap + (long)(m0 + arow) * g.lda + kt + akseg;
            ra0 = *(const uint4*)ar;
            ra1 = *(const uint4*)(ar + 8);
            if (CONV) {
                int kg = kt + bk;
                int c  = kg / 9;
                int t9 = kg - c * 9;
                int dy = (t9 / 3 - 1) * g.dil;
                int dx = (t9 % 3 - 1) * g.dil;
                const half* base = Bp + (long)c * HW;
#pragma unroll
                for (int j = 0; j < 16; j++) {
                    int p = n0 + bn0 + j;
                    int h = (p >> 6) + dy;
                    int w = (p & 63) + dx;
                    rc[j] = ((unsigned)h < 64u && (unsigned)w < 64u)
                            ? base[h * 64 + w] : __ushort_as_half((unsigned short)0);
                }
            } else if (TRANSB) {
                const half* br = Bp + (long)(n0 + arow) * g.ldb + kt + akseg;
                rb0 = *(const uint4*)br;
                rb1 = *(const uint4*)(br + 8);
            } else {
                const half* br = Bp + (long)(kt + bk) * g.ldb + n0 + bn0;
                rb0 = *(const uint4*)br;
                rb1 = *(const uint4*)(br + 8);
            }
        }

        // ---- compute tile `it-1` ----
        if (it > 0) {
            uint32_t stA = sbase + (uint32_t)(((it - 1) & 1) * STAGE_BYTES);
            uint32_t stB = stA + 128 * ROWB;
            uint32_t abase = stA + (uint32_t)(wm + rowsel) * ROWB + colsel;
            uint32_t bbase = stB + (uint32_t)(wn + rowsel) * ROWB + colsel;
#pragma unroll
            for (int ks = 0; ks < 2; ks++) {
                uint32_t af[4][4];
#pragma unroll
                for (int mt = 0; mt < 4; mt++)
                    ldsm_x4(af[mt], abase + mt * 16 * ROWB + ks * 32);
                uint32_t bf[2][4];
#pragma unroll
                for (int ntp = 0; ntp < 2; ntp++)
                    ldsm_x4(bf[ntp], bbase + ntp * 16 * ROWB + ks * 32);
#pragma unroll
                for (int mt = 0; mt < 4; mt++) {
#pragma unroll
                    for (int nt = 0; nt < 4; nt++) {
                        int ntp = nt >> 1, par = nt & 1;
                        mma_f16(acc[mt][nt],
                                af[mt][0], af[mt][1], af[mt][2], af[mt][3],
                                bf[ntp][par ? 1 : 0], bf[ntp][par ? 3 : 2]);
                    }
                }
            }
        }

        // ---- store tile `it` into stage it&1 ----
        if (it < nkt) {
            half* stA = sm + (it & 1) * STAGE_HALFS;
            half* stB = stA + 128 * LDH;
            *(uint4*)(stA + arow * LDH + akseg)     = ra0;
            *(uint4*)(stA + arow * LDH + akseg + 8) = ra1;
            if (CONV) {
#pragma unroll
                for (int j = 0; j < 16; j++)
                    stB[(bn0 + j) * LDH + bk] = rc[j];
            } else if (TRANSB) {
                *(uint4*)(stB + arow * LDH + akseg)     = rb0;
                *(uint4*)(stB + arow * LDH + akseg + 8) = rb1;
            } else {
                const half* rbh = (const half*)&rb0;
#pragma unroll
                for (int j = 0; j < 8; j++)
                    stB[(bn0 + j) * LDH + bk] = rbh[j];
                rbh = (const half*)&rb1;
#pragma unroll
                for (int j = 0; j < 8; j++)
                    stB[(bn0 + 8 + j) * LDH + bk] = rbh[j];
            }
        }
        __syncthreads();
    }

    // ---- epilogue ----
    int r  = lane >> 2;
    int cg = lane & 3;
    int mode = g.mode;
    int N = g.N;
    long bbC = (long)bb * g.sC;
    float mu = 0.f, rs = 0.f;
    if (mode == EP_QKV3 || mode == EP_ADN) { mu = g.stats[2 * bb]; rs = g.stats[2 * bb + 1]; }
    int b3 = bb / 3, t3 = bb - 3 * (bb / 3);

    auto emit = [&](float v, int m, int n) {
        long li = (long)m * N + n;
        if (mode == EP_LIN) {
            float res = v + g.bias[m];
            if (g.of)  g.of[bbC + li] = res;
            if (g.ohh) g.ohh[bbC + li] = __float2half_rn(res);
        } else if (mode == EP_GB) {
            float res = v + g.bias[m];
            if (m < 128) g.of [(long)bb * CHW + (long)m * HW + n] = res;
            else         g.of2[(long)bb * CHW + (long)(m - 128) * HW + n] = res;
        } else if (mode == EP_QKV3) {
            long ti = bbC + li;                                   // t0 index (per bz)
            long gi = (long)b3 * CHW + li;                        // gamma/beta (per batch)
            float val = (g.t0f[ti] - mu) * rs * g.gamma[gi] + v + g.betaS[gi];
            half hv = __float2half_rn(val);
            int h = n >> 6, w = n & 63;
            if (m < 64) {
                int tk = (h >> 1) * 32 + (w >> 1);
                int d  = m * 4 + (h & 1) * 2 + (w & 1);
                half* dst = (t3 == 0) ? g.d1q : (t3 == 1) ? g.d1k : g.d1v;
                dst[(long)b3 * (1024L * 256) + (long)tk * 256 + d] = hv;
            } else {
                int tk = (h >> 2) * 16 + (w >> 2);
                int d  = (m - 64) * 16 + (h & 3) * 4 + (w & 3);
                half* dst = (t3 == 0) ? g.d2q : (t3 == 1) ? g.d2k : g.d2v;
                dst[(long)b3 * (256L * 1024) + (long)tk * 1024 + d] = hv;
            }
        } else if (mode == EP_ADN) {
            long gi = bbC + li;
            float res = (g.t0f[gi] - mu) * rs * g.gamma[gi] + v + g.betaS[gi];
            g.ohh[gi] = __float2half_rn(res);
        } else if (mode == EP_SCORE) {
            g.of[bbC + li] = v * g.scale;
        } else if (mode == EP_PV1) {
            int c  = n >> 2;
            int py = (n >> 1) & 1, px = n & 1;
            int h = (m >> 5) * 2 + py, w = (m & 31) * 2 + px;
            long tgt = bbC + (long)c * HW + h * 64 + w;
            float res = g.xres[tgt] + v;
            g.of[tgt] = res;
            g.ohh[tgt] = __float2half_rn(res);
        } else if (mode == EP_PV2) {
            int c  = 64 + (n >> 4);
            int py = (n >> 2) & 3, px = n & 3;
            int h = (m >> 4) * 4 + py, w = (m & 15) * 4 + px;
            long tgt = bbC + (long)c * HW + h * 64 + w;
            float res = g.xres[tgt] + v;
            g.of[tgt] = res;
            g.ohh[tgt] = __float2half_rn(res);
        } else if (mode == EP_TANH) {
            g.of[bbC + li] = tanhf(v + g.bias[m]);
        } else if (mode == EP_GELU) {
            float u = v + g.bias[m];
            g.ohh[bbC + li] = __float2half_rn(0.5f * u * (1.f + erff(u * 0.70710678118654752f)));
        } else { // EP_FINAL
            long gi = bbC + li;
            g.of[gi] = g.midf[gi] * g.gff[gi] + v + g.bias[m];
        }
    };

#pragma unroll
    for (int mt = 0; mt < 4; mt++) {
#pragma unroll
        for (int nt = 0; nt < 4; nt++) {
            int m1 = m0 + wm + mt * 16 + r;
            int m2 = m1 + 8;
            int nn = n0 + wn + nt * 8 + cg * 2;
            emit(acc[mt][nt][0], m1, nn);
            emit(acc[mt][nt][1], m1, nn + 1);
            emit(acc[mt][nt][2], m2, nn);
            emit(acc[mt][nt][3], m2, nn + 1);
        }
    }
}

// ================= weight repack =================
__global__ void __launch_bounds__(256)
wconv_kernel(const float* qw, const float* kw, const float* vw,
             const float* e1, const float* s1, const float* b1,
             const float* e2, const float* s2, const float* b2,
             const float* sc, const float* bi1, const float* bi2) {
    int i = blockIdx.x * 256 + threadIdx.x;
    if (i >= W_TOTAL) return;
    float v;
    if (i < WO_E1) {
        int t = i >> 14, j = i & 16383;
        v = (t == 0 ? qw : t == 1 ? kw : vw)[j];
    } else if (i < WO_GB1) {
        int j = i - WO_E1, r = j / AUXK, c = j % AUXK;
        v = (c < AUXC) ? e1[r * AUXC + c] : 0.f;
    } else if (i < WO_B1) {
        int j = i - WO_GB1, r = j >> 7, c = j & 127;
        v = (r < 128) ? s1[r * 128 + c] : b1[(r - 128) * 256 + 128 + c];
    } else if (i < WO_E2) {
        v = b1[i - WO_B1];
    } else if (i < WO_GB2) {
        int j = i - WO_E2, r = j / AUXK, c = j % AUXK;
        v = (c < AUXC) ? e2[r * AUXC + c] : 0.f;
    } else if (i < WO_B2) {
        int j = i - WO_GB2, r = j >> 7, c = j & 127;
        v = (r < 128) ? s2[r * 128 + c] : b2[(r - 128) * 256 + 128 + c];
    } else if (i < WO_SC) {
        v = b2[i - WO_B2];
    } else if (i < WO_BI1) v = sc[i - WO_SC];
    else if (i < WO_BI2)   v = bi1[i - WO_BI1];
    else                   v = bi2[i - WO_BI2];
    g_wh[i] = __float2half_rn(v);
}

__global__ void __launch_bounds__(256)
biaspack_kernel(const float* qb, const float* kb, const float* vb,
                const float* s1b, const float* b1b,
                const float* s2b, const float* b2b) {
    int i = blockIdx.x * 256 + threadIdx.x;
    if (i < 384) {
        g_qkvb[i] = i < 128 ? qb[i] : i < 256 ? kb[i - 128] : vb[i - 256];
    } else if (i < 640) {
        int j = i - 384;
        g_gbb1[j] = j < 128 ? s1b[j] : b1b[j - 128];
    } else if (i < 896) {
        int j = i - 640;
        g_gbb2[j] = j < 128 ? s2b[j] : b2b[j - 128];
    }
}

// ================= concat aux (half, [b][288][HW]) =================
__global__ void __launch_bounds__(256)
concat_aux_kernel(const float* __restrict__ edge, const float* __restrict__ seg,
                  const float* __restrict__ pe,   const float* __restrict__ ps) {
    long i = (long)blockIdx.x * 256 + threadIdx.x;
    long total = (long)NB * AUXK * HW;
    if (i >= total) return;
    int p = (int)(i % HW);
    long t = i / HW;
    int c = (int)(t % AUXK);
    int b = (int)(t / AUXK);
    float v = 0.f;
    if (c < 128)       v = edge[((long)b * 128 + c) * HW + p];
    else if (c < 256)  v = seg [((long)b * 128 + (c - 128)) * HW + p];
    else if (c == 256) v = pe  [(long)b * HW + p];
    else if (c < AUXC) v = ps  [((long)b * 20 + (c - 257)) * HW + p];
    g_auxh[i] = __float2half_rn(v);
}

__global__ void __launch_bounds__(256)
cvt_f2h_kernel(const float* __restrict__ src, half* __restrict__ dst, long n) {
    long i = (long)blockIdx.x * 256 + threadIdx.x;
    if (i < n) dst[i] = __float2half_rn(src[i]);
}

// ================= LayerNorm stats =================
__global__ void __launch_bounds__(256)
ln_part_kernel(const float* __restrict__ src) {
    int b = blockIdx.y, ch = blockIdx.x;
    const int CH = CHW / 64;
    const float* p = src + (long)b * CHW + (long)ch * CH;
    int tid = threadIdx.x;
    float s = 0.f, q = 0.f;
    for (int i = tid; i < CH; i += 256) { float v = p[i]; s += v; q += v * v; }
    __shared__ float shs[8], shq[8];
#pragma unroll
    for (int o = 16; o; o >>= 1) {
        s += __shfl_xor_sync(0xffffffffu, s, o);
        q += __shfl_xor_sync(0xffffffffu, q, o);
    }
    if ((tid & 31) == 0) { shs[tid >> 5] = s; shq[tid >> 5] = q; }
    __syncthreads();
    if (tid < 8) {
        s = shs[tid]; q = shq[tid];
#pragma unroll
        for (int o = 4; o; o >>= 1) {
            s += __shfl_xor_sync(0xffu, s, o);
            q += __shfl_xor_sync(0xffu, q, o);
        }
        if (tid == 0) {
            g_part[(b * 64 + ch) * 2 + 0] = s;
            g_part[(b * 64 + ch) * 2 + 1] = q;
        }
    }
}

__global__ void ln_final_kernel() {
    int b = blockIdx.x;
    int tid = threadIdx.x;
    float s = 0.f, q = 0.f;
    for (int i = tid; i < 64; i += 32) {
        s += g_part[(b * 64 + i) * 2 + 0];
        q += g_part[(b * 64 + i) * 2 + 1];
    }
#pragma unroll
    for (int o = 16; o; o >>= 1) {
        s += __shfl_xor_sync(0xffffffffu, s, o);
        q += __shfl_xor_sync(0xffffffffu, q, o);
    }
    if (tid == 0) {
        float mu = s / (float)CHW;
        float var = q / (float)CHW - mu * mu;
        g_stats[2 * b]     = mu;
        g_stats[2 * b + 1] = rsqrtf(var + 1e-5f);
    }
}

// ================= softmax (f32 in, half out) =================
__global__ void __launch_bounds__(256)
softmax_h_kernel(const float* __restrict__ S, half* __restrict__ P, int L, int VPT) {
    long row = blockIdx.x;
    const float* p = S + row * (long)L;
    half* o = P + row * (long)L;
    int tid = threadIdx.x;
    __shared__ float sh[8];
    float v[4];
    for (int i = 0; i < VPT; i++) v[i] = p[tid + i * 256];

    float mx = -3.4e38f;
    for (int i = 0; i < VPT; i++) mx = fmaxf(mx, v[i]);
#pragma unroll
    for (int og = 16; og; og >>= 1) mx = fmaxf(mx, __shfl_xor_sync(0xffffffffu, mx, og));
    if ((tid & 31) == 0) sh[tid >> 5] = mx;
    __syncthreads();
    if (tid < 8) {
        float t = sh[tid];
#pragma unroll
        for (int og = 4; og; og >>= 1) t = fmaxf(t, __shfl_xor_sync(0xffu, t, og));
        if (tid == 0) sh[0] = t;
    }
    __syncthreads();
    mx = sh[0];
    __syncthreads();

    float s = 0.f;
    for (int i = 0; i < VPT; i++) { v[i] = __expf(v[i] - mx); s += v[i]; }
#pragma unroll
    for (int og = 16; og; og >>= 1) s += __shfl_xor_sync(0xffffffffu, s, og);
    if ((tid & 31) == 0) sh[tid >> 5] = s;
    __syncthreads();
    if (tid < 8) {
        float t = sh[tid];
#pragma unroll
        for (int og = 4; og; og >>= 1) t += __shfl_xor_sync(0xffu, t, og);
        if (tid == 0) sh[0] = t;
    }
    __syncthreads();
    float inv = 1.f / sh[0];
    for (int i = 0; i < VPT; i++) o[tid + i * 256] = __float2half_rn(v[i] * inv);
}

// ================= host =================
static void rung(bool transb, bool conv, int nT, int mT, int zT, const GP& g) {
    dim3 grid(nT, mT, zT);
    if (conv)        hgemm6<false, true ><<<grid, 256>>>(g);
    else if (transb) hgemm6<true,  false><<<grid, 256>>>(g);
    else             hgemm6<false, false><<<grid, 256>>>(g);
}

extern "C" void kernel_launch(void* const* d_in, const int* in_sizes, int n_in,
                              void* d_out, int out_size) {
    const float* x    = (const float*)d_in[0];
    const float* edge = (const float*)d_in[1];
    const float* seg  = (const float*)d_in[2];
    const float* pe   = (const float*)d_in[3];
    const float* ps   = (const float*)d_in[4];
    const float* q_w  = (const float*)d_in[5];
    const float* q_b  = (const float*)d_in[6];
    const float* k_w  = (const float*)d_in[7];
    const float* k_b  = (const float*)d_in[8];
    const float* v_w  = (const float*)d_in[9];
    const float* v_b  = (const float*)d_in[10];
    const float* d1_embed_w = (const float*)d_in[11];
    const float* d1_embed_b = (const float*)d_in[12];
    const float* d1_scale_w = (const float*)d_in[13];
    const float* d1_scale_b = (const float*)d_in[14];
    const float* d1_bias_w  = (const float*)d_in[15];
    const float* d1_bias_b  = (const float*)d_in[16];
    const float* d2_embed_w = (const float*)d_in[17];
    const float* d2_embed_b = (const float*)d_in[18];
    const float* d2_scale_w = (const float*)d_in[19];
    const float* d2_scale_b = (const float*)d_in[20];
    const float* d2_bias_w  = (const float*)d_in[21];
    const float* d2_bias_b  = (const float*)d_in[22];
    const float* sc_w  = (const float*)d_in[23];
    const float* sc_b  = (const float*)d_in[24];
    const float* bi1_w = (const float*)d_in[25];
    const float* bi1_b = (const float*)d_in[26];
    const float* bi2_w = (const float*)d_in[27];
    const float* bi2_b = (const float*)d_in[28];
    float* out = (float*)d_out;

    half *wh, *auxh, *xh, *ah, *t0h, *midh, *oh, *tmph;
    half *qp1, *kp1, *vp1, *qp2, *kp2, *vp2, *s1h, *s2h;
    float *t0f, *gam, *bet, *midf, *gf, *s1, *s2, *stats;
    float *qkvb, *gbb1, *gbb2;
    cudaGetSymbolAddress((void**)&wh,   g_wh);
    cudaGetSymbolAddress((void**)&auxh, g_auxh);
    cudaGetSymbolAddress((void**)&xh,   g_xh);
    cudaGetSymbolAddress((void**)&ah,   g_ah);
    cudaGetSymbolAddress((void**)&t0h,  g_t0h);
    cudaGetSymbolAddress((void**)&t0f,  g_t0f);
    cudaGetSymbolAddress((void**)&gam,  g_gam);
    cudaGetSymbolAddress((void**)&bet,  g_bet);
    cudaGetSymbolAddress((void**)&midh, g_midh);
    cudaGetSymbolAddress((void**)&midf, g_midf);
    cudaGetSymbolAddress((void**)&oh,   g_oh);
    cudaGetSymbolAddress((void**)&gf,   g_gf);
    cudaGetSymbolAddress((void**)&tmph, g_tmph);
    cudaGetSymbolAddress((void**)&qp1,  g_qp1);
    cudaGetSymbolAddress((void**)&kp1,  g_kp1);
    cudaGetSymbolAddress((void**)&vp1,  g_vp1);
    cudaGetSymbolAddress((void**)&qp2,  g_qp2);
    cudaGetSymbolAddress((void**)&kp2,  g_kp2);
    cudaGetSymbolAddress((void**)&vp2,  g_vp2);
    cudaGetSymbolAddress((void**)&s1,   g_s1);
    cudaGetSymbolAddress((void**)&s1h,  g_s1h);
    cudaGetSymbolAddress((void**)&s2,   g_s2);
    cudaGetSymbolAddress((void**)&s2h,  g_s2h);
    cudaGetSymbolAddress((void**)&stats, g_stats);
    cudaGetSymbolAddress((void**)&qkvb, g_qkvb);
    cudaGetSymbolAddress((void**)&gbb1, g_gbb1);
    cudaGetSymbolAddress((void**)&gbb2, g_gbb2);

    // 0. conversions / packing
    wconv_kernel<<<(W_TOTAL + 255) / 256, 256>>>(q_w, k_w, v_w,
                                                 d1_embed_w, d1_scale_w, d1_bias_w,
                                                 d2_embed_w, d2_scale_w, d2_bias_w,
                                                 sc_w, bi1_w, bi2_w);
    biaspack_kernel<<<4, 256>>>(q_b, k_b, v_b, d1_scale_b, d1_bias_b, d2_scale_b, d2_bias_b);
    cvt_f2h_kernel<<<(int)(((long)NB * CHW + 255) / 256), 256>>>(x, xh, (long)NB * CHW);
    concat_aux_kernel<<<(int)(((long)NB * AUXK * HW + 255) / 256), 256>>>(edge, seg, pe, ps);

    // 1. ADN-1 shared: a = E1(aux); gamma/betaS = GB1(a)
    {
        GP p = {};
        p.A = wh + WO_E1; p.lda = AUXK; p.sA = 0;
        p.B = auxh; p.ldb = HW; p.sB = (long)AUXK * HW;
        p.N = HW; p.sC = CHW; p.nkt = AUXK / 32; p.mode = EP_LIN;
        p.bias = d1_embed_b; p.ohh = ah;
        rung(false, false, 32, 1, NB, p);
    }
    {
        GP p = {};
        p.A = wh + WO_GB1; p.lda = 128; p.sA = 0;
        p.B = ah; p.ldb = HW; p.sB = CHW;
        p.N = HW; p.sC = CHW; p.nkt = 4; p.mode = EP_GB;
        p.bias = gbb1; p.of = gam; p.of2 = bet;
        rung(false, false, 32, 2, NB, p);
    }

    // 2. q/k/v conv1x1 merged (M=384)
    {
        GP p = {};
        p.A = wh + WO_QKV; p.lda = 128; p.sA = 0;
        p.B = xh; p.ldb = HW; p.sB = CHW;
        p.N = HW; p.sC = 3L * CHW; p.nkt = 4; p.mode = EP_LIN;
        p.bias = qkvb; p.of = t0f; p.ohh = t0h;
        rung(false, false, 32, 3, NB, p);
    }
    ln_part_kernel<<<dim3(64, 48), 256>>>(t0f);
    ln_final_kernel<<<48, 32>>>();

    // 3. ADN-apply merged (48 batches), fused patched writes
    {
        GP p = {};
        p.A = wh + WO_B1; p.lda = 256; p.sA = 0;
        p.B = t0h; p.ldb = HW; p.sB = CHW;
        p.N = HW; p.sC = CHW; p.nkt = 4; p.mode = EP_QKV3;
        p.t0f = t0f; p.gamma = gam; p.betaS = bet; p.stats = stats;
        p.d1q = qp1; p.d1k = kp1; p.d1v = vp1;
        p.d2q = qp2; p.d2k = kp2; p.d2v = vp2;
        rung(false, false, 32, 1, 48, p);
    }

    // 4. attention scale 1
    {
        GP p = {};
        p.A = qp1; p.lda = 256; p.sA = 1024L * 256;
        p.B = kp1; p.ldb = 256; p.sB = 1024L * 256;
        p.N = 1024; p.sC = 1024L * 1024; p.nkt = 8; p.mode = EP_SCORE; p.scale = 0.0625f;
        p.of = s1;
        rung(true, false, 8, 8, NB, p);
    }
    softmax_h_kernel<<<NB * 1024, 256>>>(s1, s1h, 1024, 4);
    {
        GP p = {};
        p.A = s1h; p.lda = 1024; p.sA = 1024L * 1024;
        p.B = vp1; p.ldb = 256; p.sB = 1024L * 256;
        p.N = 256; p.sC = CHW; p.nkt = 32; p.mode = EP_PV1;
        p.xres = x; p.of = midf; p.ohh = midh;
        rung(false, false, 2, 8, NB, p);
    }

    // 5. attention scale 2
    {
        GP p = {};
        p.A = qp2; p.lda = 1024; p.sA = 256L * 1024;
        p.B = kp2; p.ldb = 1024; p.sB = 256L * 1024;
        p.N = 256; p.sC = 256L * 256; p.nkt = 32; p.mode = EP_SCORE; p.scale = 0.03125f;
        p.of = s2;
        rung(true, false, 2, 2, NB, p);
    }
    softmax_h_kernel<<<NB * 256, 256>>>(s2, s2h, 256, 1);
    {
        GP p = {};
        p.A = s2h; p.lda = 256; p.sA = 256L * 256;
        p.B = vp2; p.ldb = 1024; p.sB = 256L * 1024;
        p.N = 1024; p.sC = CHW; p.nkt = 8; p.mode = EP_PV2;
        p.xres = x; p.of = midf; p.ohh = midh;
        rung(false, false, 8, 2, NB, p);
    }

    // 6. ADN-2
    {
        GP p = {};
        p.A = wh + WO_E2; p.lda = AUXK; p.sA = 0;
        p.B = auxh; p.ldb = HW; p.sB = (long)AUXK * HW;
        p.N = HW; p.sC = CHW; p.nkt = AUXK / 32; p.mode = EP_LIN;
        p.bias = d2_embed_b; p.ohh = ah;
        rung(false, false, 32, 1, NB, p);
    }
    {
        GP p = {};
        p.A = wh + WO_GB2; p.lda = 128; p.sA = 0;
        p.B = ah; p.ldb = HW; p.sB = CHW;
        p.N = HW; p.sC = CHW; p.nkt = 4; p.mode = EP_GB;
        p.bias = gbb2; p.of = gam; p.of2 = bet;
        rung(false, false, 32, 2, NB, p);
    }
    ln_part_kernel<<<dim3(64, NB), 256>>>(midf);
    ln_final_kernel<<<NB, 32>>>();
    {
        GP p = {};
        p.A = wh + WO_B2; p.lda = 256; p.sA = 0;
        p.B = midh; p.ldb = HW; p.sB = CHW;
        p.N = HW; p.sC = CHW; p.nkt = 4; p.mode = EP_ADN;
        p.t0f = midf; p.gamma = gam; p.betaS = bet; p.stats = stats;
        p.ohh = oh;
        rung(false, false, 32, 1, NB, p);
    }

    // 7. conv3x3 chain (fused gather, K=1152)
    {
        GP p = {};
        p.A = wh + WO_SC; p.lda = 1152; p.sA = 0;
        p.B = oh; p.ldb = 0; p.sB = CHW;
        p.N = HW; p.sC = CHW; p.nkt = 36; p.mode = EP_TANH; p.dil = 1;
        p.bias = sc_b; p.of = gf;
        rung(false, true, 32, 1, NB, p);
    }
    {
        GP p = {};
        p.A = wh + WO_BI1; p.lda = 1152; p.sA = 0;
        p.B = oh; p.ldb = 0; p.sB = CHW;
        p.N = HW; p.sC = CHW; p.nkt = 36; p.mode = EP_GELU; p.dil = 2;
        p.bias = bi1_b; p.ohh = tmph;
        rung(false, true, 32, 1, NB, p);
    }
    {
        GP p = {};
        p.A = wh + WO_BI2; p.lda = 1152; p.sA = 0;
        p.B = tmph; p.ldb = 0; p.sB = CHW;
        p.N = HW; p.sC = CHW; p.nkt = 36; p.mode = EP_FINAL; p.dil = 1;
        p.bias = bi2_b; p.midf = midf; p.gff = gf; p.of = out;
        rung(false, true, 32, 1, NB, p);
    }
}

// round 8
// speedup vs baseline: 1.3394x; 1.2780x over previous
#include <cuda_runtime.h>
#include <cuda_fp16.h>
#include <math.h>
#include <stdint.h>

// ---------------- problem constants ----------------
#define NB 16
#define HW 4096
#define CHW (128*HW)          // 524288
#define AUXC 277
#define AUXK 288

// ---------------- weight pack offsets (halfs) ----------------
#define WO_QKV  0             // [384][128]
#define WO_E1   49152         // [128][288]
#define WO_GB1  86016         // [256][128]
#define WO_B1   118784        // [128][256]
#define WO_E2   151552
#define WO_GB2  188416
#define WO_B2   221184
#define WO_SC   253952        // [128][1152] plane-major: k = tap*128 + c
#define WO_BI1  401408
#define WO_BI2  548864
#define W_TOTAL 696320

// ---------------- scratch ----------------
__device__ __align__(256) half  g_wh  [W_TOTAL];
__device__ float g_qkvb[384];
__device__ float g_gbb1[256];
__device__ float g_gbb2[256];
__device__ __align__(256) half  g_auxh[(long)NB*AUXK*HW];
__device__ __align__(256) half  g_xh  [(long)NB*CHW];
__device__ __align__(256) half  g_ah  [(long)NB*CHW];
__device__ __align__(256) half  g_t0h [(long)NB*3*CHW];
__device__ __align__(256) float g_t0f [(long)NB*3*CHW];
__device__ __align__(256) float g_gam [(long)NB*CHW];
__device__ __align__(256) float g_bet [(long)NB*CHW];
__device__ __align__(256) half  g_midh[(long)NB*CHW];
__device__ __align__(256) float g_midf[(long)NB*CHW];
__device__ __align__(256) half  g_oh  [(long)NB*CHW];
__device__ __align__(256) float g_gf  [(long)NB*CHW];
__device__ __align__(256) half  g_tmph[(long)NB*CHW];
__device__ __align__(256) half  g_qp1 [NB*1024L*256];
__device__ __align__(256) half  g_kp1 [NB*1024L*256];
__device__ __align__(256) half  g_vp1 [NB*1024L*256];
__device__ __align__(256) half  g_qp2 [NB*256L*1024];
__device__ __align__(256) half  g_kp2 [NB*256L*1024];
__device__ __align__(256) half  g_vp2 [NB*256L*1024];
__device__ __align__(256) half  g_s1h [NB*1024L*1024];
__device__ __align__(256) half  g_s2h [NB*256L*256];
__device__ float g_stats[96];
__device__ float g_part [48*64*2];

// ---------------- epilogue modes ----------------
#define EP_LIN   0
#define EP_GB    1
#define EP_QKV3  2
#define EP_ADN   3
#define EP_SCORE 4
#define EP_PV1   5
#define EP_PV2   6
#define EP_TANH  7
#define EP_GELU  8
#define EP_FINAL 9

// ---------------- smem geometry (halfs) ----------------
#define LDH 40                 // [row][40] for A / n-major B
#define ROWB 80
#define B_LDH 136              // [k][136] k-major B (NN path)
#define B_ROWB 272
#define STAGE_HALFS 10240      // A 128*40 + B region 5120 halfs
#define STAGE_BYTES 20480

// ---------------- asm helpers ----------------
__device__ __forceinline__ uint32_t smem_u32(const void* p) {
    uint32_t a;
    asm("{ .reg .u64 t; cvta.to.shared.u64 t, %1; cvt.u32.u64 %0, t; }" : "=r"(a) : "l"(p));
    return a;
}
__device__ __forceinline__ void ldsm_x4(uint32_t* r, uint32_t addr) {
    asm volatile("ldmatrix.sync.aligned.m8n8.x4.shared.b16 {%0,%1,%2,%3}, [%4];"
                 : "=r"(r[0]), "=r"(r[1]), "=r"(r[2]), "=r"(r[3]) : "r"(addr));
}
__device__ __forceinline__ void ldsm_x4t(uint32_t* r, uint32_t addr) {
    asm volatile("ldmatrix.sync.aligned.m8n8.x4.trans.shared.b16 {%0,%1,%2,%3}, [%4];"
                 : "=r"(r[0]), "=r"(r[1]), "=r"(r[2]), "=r"(r[3]) : "r"(addr));
}
__device__ __forceinline__ void mma_f16(float* c,
                                        uint32_t a0, uint32_t a1, uint32_t a2, uint32_t a3,
                                        uint32_t b0, uint32_t b1) {
    asm volatile(
        "mma.sync.aligned.m16n8k16.row.col.f32.f16.f16.f32 "
        "{%0,%1,%2,%3}, {%4,%5,%6,%7}, {%8,%9}, {%0,%1,%2,%3};"
        : "+f"(c[0]), "+f"(c[1]), "+f"(c[2]), "+f"(c[3])
        : "r"(a0), "r"(a1), "r"(a2), "r"(a3), "r"(b0), "r"(b1));
}

// ---------------- GEMM params ----------------
struct GP {
    const half* A; int lda; long sA;
    const half* B; int ldb; long sB;
    int N; long sC; int nkt;
    int mode; float scale; int dil;
    const float* bias;
    const float* t0f; const float* gamma; const float* betaS; const float* stats;
    const float* xres; const float* midf; const float* gff;
    float* of; float* of2; half* ohh;
    half* d1q; half* d1k; half* d1v;
    half* d2q; half* d2k; half* d2v;
};

// ================= fp16 tensor-core GEMM =================
// TRANSB=0, CONV=0 : C[m,n] = A[m,k] * B[k,n]   (B k-major smem, ldmatrix.trans)
// TRANSB=1         : C[m,n] = A[m,k] * B[n,k]   (B n-major smem, ldmatrix)
// CONV=1           : B gathered from NCHW-half activations, K=1152 plane-major
template<bool TRANSB, bool CONV>
__global__ void __launch_bounds__(256)
hgemm8(GP g) {
    __shared__ __align__(16) half sm[2 * STAGE_HALFS];
    int bb = blockIdx.z;
    int n0 = blockIdx.x * 128;
    int m0 = blockIdx.y * 128;
    const half* Ap = g.A + (long)bb * g.sA;
    const half* Bp = g.B + (long)bb * g.sB;

    int tid  = threadIdx.x;
    int lane = tid & 31;
    int warp = tid >> 5;
    int wm = (warp >> 2) * 64;
    int wn = (warp & 3) * 32;

    // A loader: row = tid>>1, k-seg = (tid&1)*16
    int arow  = tid >> 1;
    int akseg = (tid & 1) * 16;
    // B NN loader: k-row = tid>>3, n-seg = (tid&7)*16
    int bkr = tid >> 3;
    int bns = (tid & 7) * 16;
    // B CONV loader: pixel = tid&127, k-seg = (tid>>7)*16
    int cn    = tid & 127;
    int ckseg = (tid >> 7) * 16;

    uint32_t sbase = smem_u32(sm);
    int rowsel = lane & 15;
    int colsel = (lane >> 4) * 16;

    uint4 ra0, ra1, rb0, rb1;
    float acc[4][4][4] = {};
    int nkt = g.nkt;

    for (int it = 0; it <= nkt; it++) {
        // ---- global load tile `it` into registers ----
        if (it < nkt) {
            int kt = it * 32;
            const half* ar = Ap + (long)(m0 + arow) * g.lda + kt + akseg;
            ra0 = *(const uint4*)ar;
            ra1 = *(const uint4*)(ar + 8);
            if (CONV) {
                // plane-major k: tap = kt>>7, channels cb..cb+31
                int tap = kt >> 7;
                int cb  = kt & 127;
                int dy = (tap / 3 - 1) * g.dil;
                int dx = (tap % 3 - 1) * g.dil;
                int p = n0 + cn;
                int h = (p >> 6) + dy;
                int w = (p & 63) + dx;
                half rc[16];
                if ((unsigned)h < 64u && (unsigned)w < 64u) {
                    const half* base = Bp + (long)(cb + ckseg) * HW + h * 64 + w;
#pragma unroll
                    for (int j = 0; j < 16; j++) rc[j] = base[(long)j * HW];
                } else {
#pragma unroll
                    for (int j = 0; j < 16; j++) rc[j] = __ushort_as_half((unsigned short)0);
                }
                rb0 = *(uint4*)&rc[0];
                rb1 = *(uint4*)&rc[8];
            } else if (TRANSB) {
                const half* br = Bp + (long)(n0 + arow) * g.ldb + kt + akseg;
                rb0 = *(const uint4*)br;
                rb1 = *(const uint4*)(br + 8);
            } else {
                const half* br = Bp + (long)(kt + bkr) * g.ldb + n0 + bns;
                rb0 = *(const uint4*)br;
                rb1 = *(const uint4*)(br + 8);
            }
        }

        // ---- compute tile `it-1` ----
        if (it > 0) {
            uint32_t stA = sbase + (uint32_t)(((it - 1) & 1) * STAGE_BYTES);
            uint32_t stB = stA + 128 * ROWB;
            uint32_t abase = stA + (uint32_t)(wm + rowsel) * ROWB + colsel;
#pragma unroll
            for (int ks = 0; ks < 2; ks++) {
                uint32_t af[4][4];
#pragma unroll
                for (int mt = 0; mt < 4; mt++)
                    ldsm_x4(af[mt], abase + mt * 16 * ROWB + ks * 32);
                uint32_t bf[2][4];
                if (TRANSB || CONV) {
                    uint32_t bbase = stB + (uint32_t)(wn + rowsel) * ROWB + colsel;
#pragma unroll
                    for (int ntp = 0; ntp < 2; ntp++)
                        ldsm_x4(bf[ntp], bbase + ntp * 16 * ROWB + ks * 32);
                } else {
                    uint32_t bbase = stB + (uint32_t)(ks * 16 + rowsel) * B_ROWB
                                   + (uint32_t)(wn + (lane >> 4) * 8) * 2;
#pragma unroll
                    for (int ntp = 0; ntp < 2; ntp++)
                        ldsm_x4t(bf[ntp], bbase + ntp * 32);
                }
#pragma unroll
                for (int mt = 0; mt < 4; mt++) {
#pragma unroll
                    for (int nt = 0; nt < 4; nt++) {
                        int ntp = nt >> 1, par = nt & 1;
                        uint32_t b0, b1;
                        if (TRANSB || CONV) { b0 = bf[ntp][par];     b1 = bf[ntp][par + 2]; }
                        else                { b0 = bf[ntp][par * 2]; b1 = bf[ntp][par * 2 + 1]; }
                        mma_f16(acc[mt][nt],
                                af[mt][0], af[mt][1], af[mt][2], af[mt][3], b0, b1);
                    }
                }
            }
        }

        // ---- store tile `it` into stage it&1 ----
        if (it < nkt) {
            half* stA = sm + (it & 1) * STAGE_HALFS;
            half* stB = stA + 128 * LDH;
            *(uint4*)(stA + arow * LDH + akseg)     = ra0;
            *(uint4*)(stA + arow * LDH + akseg + 8) = ra1;
            if (CONV) {
                half* d = stB + cn * LDH + ckseg;
                *(uint4*)d       = rb0;
                *(uint4*)(d + 8) = rb1;
            } else if (TRANSB) {
                half* d = stB + arow * LDH + akseg;
                *(uint4*)d       = rb0;
                *(uint4*)(d + 8) = rb1;
            } else {
                half* d = stB + bkr * B_LDH + bns;
                *(uint4*)d       = rb0;
                *(uint4*)(d + 8) = rb1;
            }
        }
        __syncthreads();
    }

    // ---- epilogue ----
    int r  = lane >> 2;
    int cg = lane & 3;
    int mode = g.mode;
    int N = g.N;
    long bbC = (long)bb * g.sC;
    float mu = 0.f, rs = 0.f;
    if (mode == EP_QKV3 || mode == EP_ADN) { mu = g.stats[2 * bb]; rs = g.stats[2 * bb + 1]; }
    int b3 = bb / 3, t3 = bb - 3 * (bb / 3);

    auto emit = [&](float v, int m, int n) {
        long li = (long)m * N + n;
        if (mode == EP_LIN) {
            float res = v + g.bias[m];
            if (g.of)  g.of[bbC + li] = res;
            if (g.ohh) g.ohh[bbC + li] = __float2half_rn(res);
        } else if (mode == EP_GB) {
            float res = v + g.bias[m];
            if (m < 128) g.of [(long)bb * CHW + (long)m * HW + n] = res;
            else         g.of2[(long)bb * CHW + (long)(m - 128) * HW + n] = res;
        } else if (mode == EP_QKV3) {
            long ti = bbC + li;
            long gi = (long)b3 * CHW + li;
            float val = (g.t0f[ti] - mu) * rs * g.gamma[gi] + v + g.betaS[gi];
            half hv = __float2half_rn(val);
            int h = n >> 6, w = n & 63;
            if (m < 64) {
                int tk = (h >> 1) * 32 + (w >> 1);
                int d  = m * 4 + (h & 1) * 2 + (w & 1);
                half* dst = (t3 == 0) ? g.d1q : (t3 == 1) ? g.d1k : g.d1v;
                dst[(long)b3 * (1024L * 256) + (long)tk * 256 + d] = hv;
            } else {
                int tk = (h >> 2) * 16 + (w >> 2);
                int d  = (m - 64) * 16 + (h & 3) * 4 + (w & 3);
                half* dst = (t3 == 0) ? g.d2q : (t3 == 1) ? g.d2k : g.d2v;
                dst[(long)b3 * (256L * 1024) + (long)tk * 1024 + d] = hv;
            }
        } else if (mode == EP_ADN) {
            long gi = bbC + li;
            float res = (g.t0f[gi] - mu) * rs * g.gamma[gi] + v + g.betaS[gi];
            g.ohh[gi] = __float2half_rn(res);
        } else if (mode == EP_SCORE) {
            g.ohh[bbC + li] = __float2half_rn(v * g.scale);
        } else if (mode == EP_PV1) {
            int c  = n >> 2;
            int py = (n >> 1) & 1, px = n & 1;
            int h = (m >> 5) * 2 + py, w = (m & 31) * 2 + px;
            long tgt = bbC + (long)c * HW + h * 64 + w;
            float res = g.xres[tgt] + v;
            g.of[tgt] = res;
            g.ohh[tgt] = __float2half_rn(res);
        } else if (mode == EP_PV2) {
            int c  = 64 + (n >> 4);
            int py = (n >> 2) & 3, px = n & 3;
            int h = (m >> 4) * 4 + py, w = (m & 15) * 4 + px;
            long tgt = bbC + (long)c * HW + h * 64 + w;
            float res = g.xres[tgt] + v;
            g.of[tgt] = res;
            g.ohh[tgt] = __float2half_rn(res);
        } else if (mode == EP_TANH) {
            g.of[bbC + li] = tanhf(v + g.bias[m]);
        } else if (mode == EP_GELU) {
            float u = v + g.bias[m];
            g.ohh[bbC + li] = __float2half_rn(0.5f * u * (1.f + erff(u * 0.70710678118654752f)));
        } else { // EP_FINAL
            long gi = bbC + li;
            g.of[gi] = g.midf[gi] * g.gff[gi] + v + g.bias[m];
        }
    };

#pragma unroll
    for (int mt = 0; mt < 4; mt++) {
#pragma unroll
        for (int nt = 0; nt < 4; nt++) {
            int m1 = m0 + wm + mt * 16 + r;
            int m2 = m1 + 8;
            int nn = n0 + wn + nt * 8 + cg * 2;
            emit(acc[mt][nt][0], m1, nn);
            emit(acc[mt][nt][1], m1, nn + 1);
            emit(acc[mt][nt][2], m2, nn);
            emit(acc[mt][nt][3], m2, nn + 1);
        }
    }
}

// ================= weight repack =================
__global__ void __launch_bounds__(256)
wconv_kernel(const float* qw, const float* kw, const float* vw,
             const float* e1, const float* s1, const float* b1,
             const float* e2, const float* s2, const float* b2,
             const float* sc, const float* bi1, const float* bi2) {
    int i = blockIdx.x * 256 + threadIdx.x;
    if (i >= W_TOTAL) return;
    float v;
    if (i < WO_E1) {
        int t = i >> 14, j = i & 16383;
        v = (t == 0 ? qw : t == 1 ? kw : vw)[j];
    } else if (i < WO_GB1) {
        int j = i - WO_E1, r = j / AUXK, c = j % AUXK;
        v = (c < AUXC) ? e1[r * AUXC + c] : 0.f;
    } else if (i < WO_B1) {
        int j = i - WO_GB1, r = j >> 7, c = j & 127;
        v = (r < 128) ? s1[r * 128 + c] : b1[(r - 128) * 256 + 128 + c];
    } else if (i < WO_E2) {
        v = b1[i - WO_B1];
    } else if (i < WO_GB2) {
        int j = i - WO_E2, r = j / AUXK, c = j % AUXK;
        v = (c < AUXC) ? e2[r * AUXC + c] : 0.f;
    } else if (i < WO_B2) {
        int j = i - WO_GB2, r = j >> 7, c = j & 127;
        v = (r < 128) ? s2[r * 128 + c] : b2[(r - 128) * 256 + 128 + c];
    } else if (i < WO_SC) {
        v = b2[i - WO_B2];
    } else {
        // conv weights, plane-major: k = tap*128 + c
        int j = i - WO_SC;
        int blk = j / 147456, t = j % 147456;
        int o = t / 1152, rr = t % 1152;
        int tap = rr >> 7, c = rr & 127;
        const float* w = (blk == 0 ? sc : blk == 1 ? bi1 : bi2);
        v = w[((o * 128 + c) * 3 + tap / 3) * 3 + (tap % 3)];
    }
    g_wh[i] = __float2half_rn(v);
}

__global__ void __launch_bounds__(256)
biaspack_kernel(const float* qb, const float* kb, const float* vb,
                const float* s1b, const float* b1b,
                const float* s2b, const float* b2b) {
    int i = blockIdx.x * 256 + threadIdx.x;
    if (i < 384) {
        g_qkvb[i] = i < 128 ? qb[i] : i < 256 ? kb[i - 128] : vb[i - 256];
    } else if (i < 640) {
        int j = i - 384;
        g_gbb1[j] = j < 128 ? s1b[j] : b1b[j - 128];
    } else if (i < 896) {
        int j = i - 640;
        g_gbb2[j] = j < 128 ? s2b[j] : b2b[j - 128];
    }
}

// ================= concat aux (half, [b][288][HW]) =================
__global__ void __launch_bounds__(256)
concat_aux_kernel(const float* __restrict__ edge, const float* __restrict__ seg,
                  const float* __restrict__ pe,   const float* __restrict__ ps) {
    long i = (long)blockIdx.x * 256 + threadIdx.x;
    long total = (long)NB * AUXK * HW;
    if (i >= total) return;
    int p = (int)(i % HW);
    long t = i / HW;
    int c = (int)(t % AUXK);
    int b = (int)(t / AUXK);
    float v = 0.f;
    if (c < 128)       v = edge[((long)b * 128 + c) * HW + p];
    else if (c < 256)  v = seg [((long)b * 128 + (c - 128)) * HW + p];
    else if (c == 256) v = pe  [(long)b * HW + p];
    else if (c < AUXC) v = ps  [((long)b * 20 + (c - 257)) * HW + p];
    g_auxh[i] = __float2half_rn(v);
}

__global__ void __launch_bounds__(256)
cvt_f2h_kernel(const float* __restrict__ src, half* __restrict__ dst, long n) {
    long i = (long)blockIdx.x * 256 + threadIdx.x;
    if (i < n) dst[i] = __float2half_rn(src[i]);
}

// ================= LayerNorm stats =================
__global__ void __launch_bounds__(256)
ln_part_kernel(const float* __restrict__ src) {
    int b = blockIdx.y, ch = blockIdx.x;
    const int CH = CHW / 64;
    const float* p = src + (long)b * CHW + (long)ch * CH;
    int tid = threadIdx.x;
    float s = 0.f, q = 0.f;
    for (int i = tid; i < CH; i += 256) { float v = p[i]; s += v; q += v * v; }
    __shared__ float shs[8], shq[8];
#pragma unroll
    for (int o = 16; o; o >>= 1) {
        s += __shfl_xor_sync(0xffffffffu, s, o);
        q += __shfl_xor_sync(0xffffffffu, q, o);
    }
    if ((tid & 31) == 0) { shs[tid >> 5] = s; shq[tid >> 5] = q; }
    __syncthreads();
    if (tid < 8) {
        s = shs[tid]; q = shq[tid];
#pragma unroll
        for (int o = 4; o; o >>= 1) {
            s += __shfl_xor_sync(0xffu, s, o);
            q += __shfl_xor_sync(0xffu, q, o);
        }
        if (tid == 0) {
            g_part[(b * 64 + ch) * 2 + 0] = s;
            g_part[(b * 64 + ch) * 2 + 1] = q;
        }
    }
}

__global__ void ln_final_kernel() {
    int b = blockIdx.x;
    int tid = threadIdx.x;
    float s = 0.f, q = 0.f;
    for (int i = tid; i < 64; i += 32) {
        s += g_part[(b * 64 + i) * 2 + 0];
        q += g_part[(b * 64 + i) * 2 + 1];
    }
#pragma unroll
    for (int o = 16; o; o >>= 1) {
        s += __shfl_xor_sync(0xffffffffu, s, o);
        q += __shfl_xor_sync(0xffffffffu, q, o);
    }
    if (tid == 0) {
        float mu = s / (float)CHW;
        float var = q / (float)CHW - mu * mu;
        g_stats[2 * b]     = mu;
        g_stats[2 * b + 1] = rsqrtf(var + 1e-5f);
    }
}

// ================= softmax (half in, half out) =================
__global__ void __launch_bounds__(256)
softmax_hh_kernel(const half* __restrict__ S, half* __restrict__ P, int L, int VPT) {
    long row = blockIdx.x;
    const half* p = S + row * (long)L;
    half* o = P + row * (long)L;
    int tid = threadIdx.x;
    __shared__ float sh[8];
    float v[4];
    for (int i = 0; i < VPT; i++) v[i] = __half2float(p[tid + i * 256]);

    float mx = -3.4e38f;
    for (int i = 0; i < VPT; i++) mx = fmaxf(mx, v[i]);
#pragma unroll
    for (int og = 16; og; og >>= 1) mx = fmaxf(mx, __shfl_xor_sync(0xffffffffu, mx, og));
    if ((tid & 31) == 0) sh[tid >> 5] = mx;
    __syncthreads();
    if (tid < 8) {
        float t = sh[tid];
#pragma unroll
        for (int og = 4; og; og >>= 1) t = fmaxf(t, __shfl_xor_sync(0xffu, t, og));
        if (tid == 0) sh[0] = t;
    }
    __syncthreads();
    mx = sh[0];
    __syncthreads();

    float s = 0.f;
    for (int i = 0; i < VPT; i++) { v[i] = __expf(v[i] - mx); s += v[i]; }
#pragma unroll
    for (int og = 16; og; og >>= 1) s += __shfl_xor_sync(0xffffffffu, s, og);
    if ((tid & 31) == 0) sh[tid >> 5] = s;
    __syncthreads();
    if (tid < 8) {
        float t = sh[tid];
#pragma unroll
        for (int og = 4; og; og >>= 1) t += __shfl_xor_sync(0xffu, t, og);
        if (tid == 0) sh[0] = t;
    }
    __syncthreads();
    float inv = 1.f / sh[0];
    for (int i = 0; i < VPT; i++) o[tid + i * 256] = __float2half_rn(v[i] * inv);
}

// ================= host =================
static void rung(bool transb, bool conv, int nT, int mT, int zT, const GP& g) {
    dim3 grid(nT, mT, zT);
    if (conv)        hgemm8<false, true ><<<grid, 256>>>(g);
    else if (transb) hgemm8<true,  false><<<grid, 256>>>(g);
    else             hgemm8<false, false><<<grid, 256>>>(g);
}

extern "C" void kernel_launch(void* const* d_in, const int* in_sizes, int n_in,
                              void* d_out, int out_size) {
    const float* x    = (const float*)d_in[0];
    const float* edge = (const float*)d_in[1];
    const float* seg  = (const float*)d_in[2];
    const float* pe   = (const float*)d_in[3];
    const float* ps   = (const float*)d_in[4];
    const float* q_w  = (const float*)d_in[5];
    const float* q_b  = (const float*)d_in[6];
    const float* k_w  = (const float*)d_in[7];
    const float* k_b  = (const float*)d_in[8];
    const float* v_w  = (const float*)d_in[9];
    const float* v_b  = (const float*)d_in[10];
    const float* d1_embed_w = (const float*)d_in[11];
    const float* d1_embed_b = (const float*)d_in[12];
    const float* d1_scale_w = (const float*)d_in[13];
    const float* d1_scale_b = (const float*)d_in[14];
    const float* d1_bias_w  = (const float*)d_in[15];
    const float* d1_bias_b  = (const float*)d_in[16];
    const float* d2_embed_w = (const float*)d_in[17];
    const float* d2_embed_b = (const float*)d_in[18];
    const float* d2_scale_w = (const float*)d_in[19];
    const float* d2_scale_b = (const float*)d_in[20];
    const float* d2_bias_w  = (const float*)d_in[21];
    const float* d2_bias_b  = (const float*)d_in[22];
    const float* sc_w  = (const float*)d_in[23];
    const float* sc_b  = (const float*)d_in[24];
    const float* bi1_w = (const float*)d_in[25];
    const float* bi1_b = (const float*)d_in[26];
    const float* bi2_w = (const float*)d_in[27];
    const float* bi2_b = (const float*)d_in[28];
    float* out = (float*)d_out;

    half *wh, *auxh, *xh, *ah, *t0h, *midh, *oh, *tmph;
    half *qp1, *kp1, *vp1, *qp2, *kp2, *vp2, *s1h, *s2h;
    float *t0f, *gam, *bet, *midf, *gf, *stats;
    float *qkvb, *gbb1, *gbb2;
    cudaGetSymbolAddress((void**)&wh,   g_wh);
    cudaGetSymbolAddress((void**)&auxh, g_auxh);
    cudaGetSymbolAddress((void**)&xh,   g_xh);
    cudaGetSymbolAddress((void**)&ah,   g_ah);
    cudaGetSymbolAddress((void**)&t0h,  g_t0h);
    cudaGetSymbolAddress((void**)&t0f,  g_t0f);
    cudaGetSymbolAddress((void**)&gam,  g_gam);
    cudaGetSymbolAddress((void**)&bet,  g_bet);
    cudaGetSymbolAddress((void**)&midh, g_midh);
    cudaGetSymbolAddress((void**)&midf, g_midf);
    cudaGetSymbolAddress((void**)&oh,   g_oh);
    cudaGetSymbolAddress((void**)&gf,   g_gf);
    cudaGetSymbolAddress((void**)&tmph, g_tmph);
    cudaGetSymbolAddress((void**)&qp1,  g_qp1);
    cudaGetSymbolAddress((void**)&kp1,  g_kp1);
    cudaGetSymbolAddress((void**)&vp1,  g_vp1);
    cudaGetSymbolAddress((void**)&qp2,  g_qp2);
    cudaGetSymbolAddress((void**)&kp2,  g_kp2);
    cudaGetSymbolAddress((void**)&vp2,  g_vp2);
    cudaGetSymbolAddress((void**)&s1h,  g_s1h);
    cudaGetSymbolAddress((void**)&s2h,  g_s2h);
    cudaGetSymbolAddress((void**)&stats, g_stats);
    cudaGetSymbolAddress((void**)&qkvb, g_qkvb);
    cudaGetSymbolAddress((void**)&gbb1, g_gbb1);
    cudaGetSymbolAddress((void**)&gbb2, g_gbb2);

    // 0. conversions / packing
    wconv_kernel<<<(W_TOTAL + 255) / 256, 256>>>(q_w, k_w, v_w,
                                                 d1_embed_w, d1_scale_w, d1_bias_w,
                                                 d2_embed_w, d2_scale_w, d2_bias_w,
                                                 sc_w, bi1_w, bi2_w);
    biaspack_kernel<<<4, 256>>>(q_b, k_b, v_b, d1_scale_b, d1_bias_b, d2_scale_b, d2_bias_b);
    cvt_f2h_kernel<<<(int)(((long)NB * CHW + 255) / 256), 256>>>(x, xh, (long)NB * CHW);
    concat_aux_kernel<<<(int)(((long)NB * AUXK * HW + 255) / 256), 256>>>(edge, seg, pe, ps);

    // 1. ADN-1 shared: a = E1(aux); gamma/betaS = GB1(a)
    {
        GP p = {};
        p.A = wh + WO_E1; p.lda = AUXK; p.sA = 0;
        p.B = auxh; p.ldb = HW; p.sB = (long)AUXK * HW;
        p.N = HW; p.sC = CHW; p.nkt = AUXK / 32; p.mode = EP_LIN;
        p.bias = d1_embed_b; p.ohh = ah;
        rung(false, false, 32, 1, NB, p);
    }
    {
        GP p = {};
        p.A = wh + WO_GB1; p.lda = 128; p.sA = 0;
        p.B = ah; p.ldb = HW; p.sB = CHW;
        p.N = HW; p.sC = CHW; p.nkt = 4; p.mode = EP_GB;
        p.bias = gbb1; p.of = gam; p.of2 = bet;
        rung(false, false, 32, 2, NB, p);
    }

    // 2. q/k/v conv1x1 merged (M=384)
    {
        GP p = {};
        p.A = wh + WO_QKV; p.lda = 128; p.sA = 0;
        p.B = xh; p.ldb = HW; p.sB = CHW;
        p.N = HW; p.sC = 3L * CHW; p.nkt = 4; p.mode = EP_LIN;
        p.bias = qkvb; p.of = t0f; p.ohh = t0h;
        rung(false, false, 32, 3, NB, p);
    }
    ln_part_kernel<<<dim3(64, 48), 256>>>(t0f);
    ln_final_kernel<<<48, 32>>>();

    // 3. ADN-apply merged (48 batches), fused patched writes
    {
        GP p = {};
        p.A = wh + WO_B1; p.lda = 256; p.sA = 0;
        p.B = t0h; p.ldb = HW; p.sB = CHW;
        p.N = HW; p.sC = CHW; p.nkt = 4; p.mode = EP_QKV3;
        p.t0f = t0f; p.gamma = gam; p.betaS = bet; p.stats = stats;
        p.d1q = qp1; p.d1k = kp1; p.d1v = vp1;
        p.d2q = qp2; p.d2k = kp2; p.d2v = vp2;
        rung(false, false, 32, 1, 48, p);
    }

    // 4. attention scale 1
    {
        GP p = {};
        p.A = qp1; p.lda = 256; p.sA = 1024L * 256;
        p.B = kp1; p.ldb = 256; p.sB = 1024L * 256;
        p.N = 1024; p.sC = 1024L * 1024; p.nkt = 8; p.mode = EP_SCORE; p.scale = 0.0625f;
        p.ohh = s1h;
        rung(true, false, 8, 8, NB, p);
    }
    softmax_hh_kernel<<<NB * 1024, 256>>>(s1h, s1h, 1024, 4);
    {
        GP p = {};
        p.A = s1h; p.lda = 1024; p.sA = 1024L * 1024;
        p.B = vp1; p.ldb = 256; p.sB = 1024L * 256;
        p.N = 256; p.sC = CHW; p.nkt = 32; p.mode = EP_PV1;
        p.xres = x; p.of = midf; p.ohh = midh;
        rung(false, false, 2, 8, NB, p);
    }

    // 5. attention scale 2
    {
        GP p = {};
        p.A = qp2; p.lda = 1024; p.sA = 256L * 1024;
        p.B = kp2; p.ldb = 1024; p.sB = 256L * 1024;
        p.N = 256; p.sC = 256L * 256; p.nkt = 32; p.mode = EP_SCORE; p.scale = 0.03125f;
        p.ohh = s2h;
        rung(true, false, 2, 2, NB, p);
    }
    softmax_hh_kernel<<<NB * 256, 256>>>(s2h, s2h, 256, 1);
    {
        GP p = {};
        p.A = s2h; p.lda = 256; p.sA = 256L * 256;
        p.B = vp2; p.ldb = 1024; p.sB = 256L * 1024;
        p.N = 1024; p.sC = CHW; p.nkt = 8; p.mode = EP_PV2;
        p.xres = x; p.of = midf; p.ohh = midh;
        rung(false, false, 8, 2, NB, p);
    }

    // 6. ADN-2
    {
        GP p = {};
        p.A = wh + WO_E2; p.lda = AUXK; p.sA = 0;
        p.B = auxh; p.ldb = HW; p.sB = (long)AUXK * HW;
        p.N = HW; p.sC = CHW; p.nkt = AUXK / 32; p.mode = EP_LIN;
        p.bias = d2_embed_b; p.ohh = ah;
        rung(false, false, 32, 1, NB, p);
    }
    {
        GP p = {};
        p.A = wh + WO_GB2; p.lda = 128; p.sA = 0;
        p.B = ah; p.ldb = HW; p.sB = CHW;
        p.N = HW; p.sC = CHW; p.nkt = 4; p.mode = EP_GB;
        p.bias = gbb2; p.of = gam; p.of2 = bet;
        rung(false, false, 32, 2, NB, p);
    }
    ln_part_kernel<<<dim3(64, NB), 256>>>(midf);
    ln_final_kernel<<<NB, 32>>>();
    {
        GP p = {};
        p.A = wh + WO_B2; p.lda = 256; p.sA = 0;
        p.B = midh; p.ldb = HW; p.sB = CHW;
        p.N = HW; p.sC = CHW; p.nkt = 4; p.mode = EP_ADN;
        p.t0f = midf; p.gamma = gam; p.betaS = bet; p.stats = stats;
        p.ohh = oh;
        rung(false, false, 32, 1, NB, p);
    }

    // 7. conv3x3 chain (coalesced plane-major gather, K=1152)
    {
        GP p = {};
        p.A = wh + WO_SC; p.lda = 1152; p.sA = 0;
        p.B = oh; p.ldb = 0; p.sB = CHW;
        p.N = HW; p.sC = CHW; p.nkt = 36; p.mode = EP_TANH; p.dil = 1;
        p.bias = sc_b; p.of = gf;
        rung(false, true, 32, 1, NB, p);
    }
    {
        GP p = {};
        p.A = wh + WO_BI1; p.lda = 1152; p.sA = 0;
        p.B = oh; p.ldb = 0; p.sB = CHW;
        p.N = HW; p.sC = CHW; p.nkt = 36; p.mode = EP_GELU; p.dil = 2;
        p.bias = bi1_b; p.ohh = tmph;
        rung(false, true, 32, 1, NB, p);
    }
    {
        GP p = {};
        p.A = wh + WO_BI2; p.lda = 1152; p.sA = 0;
        p.B = tmph; p.ldb = 0; p.sB = CHW;
        p.N = HW; p.sC = CHW; p.nkt = 36; p.mode = EP_FINAL; p.dil = 1;
        p.bias = bi2_b; p.midf = midf; p.gff = gf; p.of = out;
        rung(false, true, 32, 1, NB, p);
    }
}

// round 9
// speedup vs baseline: 1.3954x; 1.0418x over previous
#include <cuda_runtime.h>
#include <cuda_fp16.h>
#include <math.h>
#include <stdint.h>

// ---------------- problem constants ----------------
#define NB 16
#define HW 4096
#define CHW (128*HW)          // 524288
#define AUXC 277
#define AUXK 320              // padded to multiple of 64

// ---------------- weight pack offsets (halfs) ----------------
#define WO_QKV  0             // [384][128]
#define WO_E1   49152         // [128][320]
#define WO_GB1  90112         // [256][128]
#define WO_B1   122880        // [128][256]
#define WO_E2   155648
#define WO_GB2  196608
#define WO_B2   229376
#define WO_SC   262144        // [128][1152] plane-major: k = tap*128 + c
#define WO_BI1  409600
#define WO_BI2  557056
#define W_TOTAL 704512

// ---------------- scratch ----------------
__device__ __align__(256) half  g_wh  [W_TOTAL];
__device__ float g_qkvb[384];
__device__ float g_gbb1[256];
__device__ float g_gbb2[256];
__device__ __align__(256) half  g_auxh[(long)NB*AUXK*HW];
__device__ __align__(256) half  g_xh  [(long)NB*CHW];
__device__ __align__(256) half  g_ah  [(long)NB*CHW];
__device__ __align__(256) half  g_t0h [(long)NB*3*CHW];
__device__ __align__(256) float g_t0f [(long)NB*3*CHW];
__device__ __align__(256) float g_gam [(long)NB*CHW];
__device__ __align__(256) float g_bet [(long)NB*CHW];
__device__ __align__(256) half  g_midh[(long)NB*CHW];
__device__ __align__(256) float g_midf[(long)NB*CHW];
__device__ __align__(256) half  g_oh  [(long)NB*CHW];
__device__ __align__(256) float g_gf  [(long)NB*CHW];
__device__ __align__(256) half  g_tmph[(long)NB*CHW];
__device__ __align__(256) half  g_qp1 [NB*1024L*256];
__device__ __align__(256) half  g_kp1 [NB*1024L*256];
__device__ __align__(256) half  g_vp1 [NB*1024L*256];
__device__ __align__(256) half  g_qp2 [NB*256L*1024];
__device__ __align__(256) half  g_kp2 [NB*256L*1024];
__device__ __align__(256) half  g_vp2 [NB*256L*1024];
__device__ __align__(256) half  g_s1h [NB*1024L*1024];
__device__ __align__(256) half  g_s2h [NB*256L*256];
__device__ float g_stats[96];
__device__ float g_part [48*64*2];

// ---------------- epilogue modes ----------------
#define EP_LIN   0
#define EP_GB    1
#define EP_QKV3  2
#define EP_ADN   3
#define EP_SCORE 4
#define EP_PV1   5
#define EP_PV2   6
#define EP_TANH  7
#define EP_GELU  8
#define EP_FINAL 9

// ---------------- smem geometry (halfs), Kt = 64 ----------------
#define A_LDH 72               // 64 + 8 pad
#define A_ROWB 144
#define BK_LDH 136             // k-major B rows: 128 + 8 pad
#define BK_ROWB 272
#define STAGE_HALFS 18432      // A 128*72 (9216) + B region 9216
#define STAGE_BYTES 36864
#define B_OFF_H 9216
#define GSM_BYTES (2*STAGE_BYTES)   // 73728

// ---------------- asm helpers ----------------
__device__ __forceinline__ uint32_t smem_u32(const void* p) {
    uint32_t a;
    asm("{ .reg .u64 t; cvta.to.shared.u64 t, %1; cvt.u32.u64 %0, t; }" : "=r"(a) : "l"(p));
    return a;
}
__device__ __forceinline__ void ldsm_x4(uint32_t* r, uint32_t addr) {
    asm volatile("ldmatrix.sync.aligned.m8n8.x4.shared.b16 {%0,%1,%2,%3}, [%4];"
                 : "=r"(r[0]), "=r"(r[1]), "=r"(r[2]), "=r"(r[3]) : "r"(addr));
}
__device__ __forceinline__ void ldsm_x4t(uint32_t* r, uint32_t addr) {
    asm volatile("ldmatrix.sync.aligned.m8n8.x4.trans.shared.b16 {%0,%1,%2,%3}, [%4];"
                 : "=r"(r[0]), "=r"(r[1]), "=r"(r[2]), "=r"(r[3]) : "r"(addr));
}
__device__ __forceinline__ void mma_f16(float* c,
                                        uint32_t a0, uint32_t a1, uint32_t a2, uint32_t a3,
                                        uint32_t b0, uint32_t b1) {
    asm volatile(
        "mma.sync.aligned.m16n8k16.row.col.f32.f16.f16.f32 "
        "{%0,%1,%2,%3}, {%4,%5,%6,%7}, {%8,%9}, {%0,%1,%2,%3};"
        : "+f"(c[0]), "+f"(c[1]), "+f"(c[2]), "+f"(c[3])
        : "r"(a0), "r"(a1), "r"(a2), "r"(a3), "r"(b0), "r"(b1));
}

// ---------------- GEMM params ----------------
struct GP {
    const half* A; int lda; long sA;
    const half* B; int ldb; long sB;
    int N; long sC; int nkt;               // nkt = K/64
    int mode; float scale; int dil;
    const float* bias;
    const float* t0f; const float* gamma; const float* betaS; const float* stats;
    const float* xres; const float* midf; const float* gff;
    float* of; float* of2; half* ohh;
    half* d1q; half* d1k; half* d1v;
    half* d2q; half* d2k; half* d2v;
};

// ================= fp16 tensor-core GEMM, Kt=64 =================
// TRANSB=0, CONV=0 : C[m,n] = A[m,k] * B[k,n]   (B k-major smem, ldmatrix.trans)
// TRANSB=1         : C[m,n] = A[m,k] * B[n,k]   (B n-major smem, ldmatrix)
// CONV=1           : B gathered from NCHW-half activations, K=1152 plane-major
template<bool TRANSB, bool CONV>
__global__ void __launch_bounds__(256)
hgemm9(GP g) {
    extern __shared__ __align__(16) half sm[];
    int bb = blockIdx.z;
    int n0 = blockIdx.x * 128;
    int m0 = blockIdx.y * 128;
    const half* Ap = g.A + (long)bb * g.sA;
    const half* Bp = g.B + (long)bb * g.sB;

    int tid  = threadIdx.x;
    int lane = tid & 31;
    int warp = tid >> 5;
    int wm = (warp >> 2) * 64;
    int wn = (warp & 3) * 32;

    // A loader: row = tid>>1, k-seg = (tid&1)*32
    int arow  = tid >> 1;
    int akseg = (tid & 1) * 32;
    // B NN loader: k-row = tid>>2 (64 rows), n-seg = (tid&3)*32
    int bkr = tid >> 2;
    int bns = (tid & 3) * 32;
    // B CONV loader: pixel = tid&127, channel seg = (tid>>7)*32
    int cn    = tid & 127;
    int ckseg = (tid >> 7) * 32;

    uint32_t sbase = smem_u32(sm);
    int rowsel = lane & 15;
    int colsel = (lane >> 4) * 16;

    uint4 ra[4], rb[4];
    float acc[4][4][4] = {};
    int nkt = g.nkt;

    for (int it = 0; it <= nkt; it++) {
        // ---- global load tile `it` into registers ----
        if (it < nkt) {
            int kt = it * 64;
            const half* ar = Ap + (long)(m0 + arow) * g.lda + kt + akseg;
#pragma unroll
            for (int j = 0; j < 4; j++) ra[j] = *(const uint4*)(ar + j * 8);
            if (CONV) {
                int tap = kt >> 7;
                int cb  = (kt & 127) + ckseg;
                int dy = (tap / 3 - 1) * g.dil;
                int dx = (tap % 3 - 1) * g.dil;
                int p = n0 + cn;
                int h = (p >> 6) + dy;
                int w = (p & 63) + dx;
                half rc[32];
                if ((unsigned)h < 64u && (unsigned)w < 64u) {
                    const half* base = Bp + (long)cb * HW + h * 64 + w;
#pragma unroll
                    for (int j = 0; j < 32; j++) rc[j] = base[(long)j * HW];
                } else {
#pragma unroll
                    for (int j = 0; j < 32; j++) rc[j] = __ushort_as_half((unsigned short)0);
                }
#pragma unroll
                for (int j = 0; j < 4; j++) rb[j] = ((uint4*)rc)[j];
            } else if (TRANSB) {
                const half* br = Bp + (long)(n0 + arow) * g.ldb + kt + akseg;
#pragma unroll
                for (int j = 0; j < 4; j++) rb[j] = *(const uint4*)(br + j * 8);
            } else {
                const half* br = Bp + (long)(kt + bkr) * g.ldb + n0 + bns;
#pragma unroll
                for (int j = 0; j < 4; j++) rb[j] = *(const uint4*)(br + j * 8);
            }
        }

        // ---- compute tile `it-1` ----
        if (it > 0) {
            uint32_t stA = sbase + (uint32_t)(((it - 1) & 1) * STAGE_BYTES);
            uint32_t stB = stA + B_OFF_H * 2;
            uint32_t abase = stA + (uint32_t)(wm + rowsel) * A_ROWB + colsel;
#pragma unroll
            for (int ks = 0; ks < 4; ks++) {
                uint32_t af[4][4];
#pragma unroll
                for (int mt = 0; mt < 4; mt++)
                    ldsm_x4(af[mt], abase + mt * 16 * A_ROWB + ks * 32);
                uint32_t bf[2][4];
                if (TRANSB || CONV) {
                    uint32_t bbase = stB + (uint32_t)(wn + rowsel) * A_ROWB + colsel;
#pragma unroll
                    for (int ntp = 0; ntp < 2; ntp++)
                        ldsm_x4(bf[ntp], bbase + ntp * 16 * A_ROWB + ks * 32);
                } else {
                    uint32_t bbase = stB + (uint32_t)(ks * 16 + rowsel) * BK_ROWB
                                   + (uint32_t)(wn + (lane >> 4) * 8) * 2;
#pragma unroll
                    for (int ntp = 0; ntp < 2; ntp++)
                        ldsm_x4t(bf[ntp], bbase + ntp * 32);
                }
#pragma unroll
                for (int mt = 0; mt < 4; mt++) {
#pragma unroll
                    for (int nt = 0; nt < 4; nt++) {
                        int ntp = nt >> 1, par = nt & 1;
                        uint32_t b0, b1;
                        if (TRANSB || CONV) { b0 = bf[ntp][par];     b1 = bf[ntp][par + 2]; }
                        else                { b0 = bf[ntp][par * 2]; b1 = bf[ntp][par * 2 + 1]; }
                        mma_f16(acc[mt][nt],
                                af[mt][0], af[mt][1], af[mt][2], af[mt][3], b0, b1);
                    }
                }
            }
        }

        // ---- store tile `it` into stage it&1 ----
        if (it < nkt) {
            half* stA = sm + (it & 1) * STAGE_HALFS;
            half* stB = stA + B_OFF_H;
            half* da = stA + arow * A_LDH + akseg;
#pragma unroll
            for (int j = 0; j < 4; j++) *(uint4*)(da + j * 8) = ra[j];
            half* db;
            if (CONV)        db = stB + cn * A_LDH + ckseg;
            else if (TRANSB) db = stB + arow * A_LDH + akseg;
            else             db = stB + bkr * BK_LDH + bns;
#pragma unroll
            for (int j = 0; j < 4; j++) *(uint4*)(db + j * 8) = rb[j];
        }
        __syncthreads();
    }

    // ---- epilogue ----
    int r  = lane >> 2;
    int cg = lane & 3;
    int mode = g.mode;
    int N = g.N;
    long bbC = (long)bb * g.sC;
    float mu = 0.f, rs = 0.f;
    if (mode == EP_QKV3 || mode == EP_ADN) { mu = g.stats[2 * bb]; rs = g.stats[2 * bb + 1]; }
    int b3 = bb / 3, t3 = bb - 3 * (bb / 3);

    auto emit = [&](float v, int m, int n) {
        long li = (long)m * N + n;
        if (mode == EP_LIN) {
            float res = v + g.bias[m];
            if (g.of)  g.of[bbC + li] = res;
            if (g.ohh) g.ohh[bbC + li] = __float2half_rn(res);
        } else if (mode == EP_GB) {
            float res = v + g.bias[m];
            if (m < 128) g.of [(long)bb * CHW + (long)m * HW + n] = res;
            else         g.of2[(long)bb * CHW + (long)(m - 128) * HW + n] = res;
        } else if (mode == EP_QKV3) {
            long ti = bbC + li;
            long gi = (long)b3 * CHW + li;
            float val = (g.t0f[ti] - mu) * rs * g.gamma[gi] + v + g.betaS[gi];
            half hv = __float2half_rn(val);
            int h = n >> 6, w = n & 63;
            if (m < 64) {
                int tk = (h >> 1) * 32 + (w >> 1);
                int d  = m * 4 + (h & 1) * 2 + (w & 1);
                half* dst = (t3 == 0) ? g.d1q : (t3 == 1) ? g.d1k : g.d1v;
                dst[(long)b3 * (1024L * 256) + (long)tk * 256 + d] = hv;
            } else {
                int tk = (h >> 2) * 16 + (w >> 2);
                int d  = (m - 64) * 16 + (h & 3) * 4 + (w & 3);
                half* dst = (t3 == 0) ? g.d2q : (t3 == 1) ? g.d2k : g.d2v;
                dst[(long)b3 * (256L * 1024) + (long)tk * 1024 + d] = hv;
            }
        } else if (mode == EP_ADN) {
            long gi = bbC + li;
            float res = (g.t0f[gi] - mu) * rs * g.gamma[gi] + v + g.betaS[gi];
            g.ohh[gi] = __float2half_rn(res);
        } else if (mode == EP_SCORE) {
            g.ohh[bbC + li] = __float2half_rn(v * g.scale);
        } else if (mode == EP_PV1) {
            int c  = n >> 2;
            int py = (n >> 1) & 1, px = n & 1;
            int h = (m >> 5) * 2 + py, w = (m & 31) * 2 + px;
            long tgt = bbC + (long)c * HW + h * 64 + w;
            float res = g.xres[tgt] + v;
            g.of[tgt] = res;
            g.ohh[tgt] = __float2half_rn(res);
        } else if (mode == EP_PV2) {
            int c  = 64 + (n >> 4);
            int py = (n >> 2) & 3, px = n & 3;
            int h = (m >> 4) * 4 + py, w = (m & 15) * 4 + px;
            long tgt = bbC + (long)c * HW + h * 64 + w;
            float res = g.xres[tgt] + v;
            g.of[tgt] = res;
            g.ohh[tgt] = __float2half_rn(res);
        } else if (mode == EP_TANH) {
            g.of[bbC + li] = tanhf(v + g.bias[m]);
        } else if (mode == EP_GELU) {
            float u = v + g.bias[m];
            g.ohh[bbC + li] = __float2half_rn(0.5f * u * (1.f + erff(u * 0.70710678118654752f)));
        } else { // EP_FINAL
            long gi = bbC + li;
            g.of[gi] = g.midf[gi] * g.gff[gi] + v + g.bias[m];
        }
    };

#pragma unroll
    for (int mt = 0; mt < 4; mt++) {
#pragma unroll
        for (int nt = 0; nt < 4; nt++) {
            int m1 = m0 + wm + mt * 16 + r;
            int m2 = m1 + 8;
            int nn = n0 + wn + nt * 8 + cg * 2;
            emit(acc[mt][nt][0], m1, nn);
            emit(acc[mt][nt][1], m1, nn + 1);
            emit(acc[mt][nt][2], m2, nn);
            emit(acc[mt][nt][3], m2, nn + 1);
        }
    }
}

// ================= weight repack =================
__global__ void __launch_bounds__(256)
wconv_kernel(const float* qw, const float* kw, const float* vw,
             const float* e1, const float* s1, const float* b1,
             const float* e2, const float* s2, const float* b2,
             const float* sc, const float* bi1, const float* bi2) {
    int i = blockIdx.x * 256 + threadIdx.x;
    if (i >= W_TOTAL) return;
    float v;
    if (i < WO_E1) {
        int t = i >> 14, j = i & 16383;
        v = (t == 0 ? qw : t == 1 ? kw : vw)[j];
    } else if (i < WO_GB1) {
        int j = i - WO_E1, r = j / AUXK, c = j % AUXK;
        v = (c < AUXC) ? e1[r * AUXC + c] : 0.f;
    } else if (i < WO_B1) {
        int j = i - WO_GB1, r = j >> 7, c = j & 127;
        v = (r < 128) ? s1[r * 128 + c] : b1[(r - 128) * 256 + 128 + c];
    } else if (i < WO_E2) {
        v = b1[i - WO_B1];
    } else if (i < WO_GB2) {
        int j = i - WO_E2, r = j / AUXK, c = j % AUXK;
        v = (c < AUXC) ? e2[r * AUXC + c] : 0.f;
    } else if (i < WO_B2) {
        int j = i - WO_GB2, r = j >> 7, c = j & 127;
        v = (r < 128) ? s2[r * 128 + c] : b2[(r - 128) * 256 + 128 + c];
    } else if (i < WO_SC) {
        v = b2[i - WO_B2];
    } else {
        int j = i - WO_SC;
        int blk = j / 147456, t = j % 147456;
        int o = t / 1152, rr = t % 1152;
        int tap = rr >> 7, c = rr & 127;
        const float* w = (blk == 0 ? sc : blk == 1 ? bi1 : bi2);
        v = w[((o * 128 + c) * 3 + tap / 3) * 3 + (tap % 3)];
    }
    g_wh[i] = __float2half_rn(v);
}

__global__ void __launch_bounds__(256)
biaspack_kernel(const float* qb, const float* kb, const float* vb,
                const float* s1b, const float* b1b,
                const float* s2b, const float* b2b) {
    int i = blockIdx.x * 256 + threadIdx.x;
    if (i < 384) {
        g_qkvb[i] = i < 128 ? qb[i] : i < 256 ? kb[i - 128] : vb[i - 256];
    } else if (i < 640) {
        int j = i - 384;
        g_gbb1[j] = j < 128 ? s1b[j] : b1b[j - 128];
    } else if (i < 896) {
        int j = i - 640;
        g_gbb2[j] = j < 128 ? s2b[j] : b2b[j - 128];
    }
}

// ================= concat aux (vectorized row copy, [b][320][HW]) =================
__global__ void __launch_bounds__(256)
concat_aux_kernel(const float* __restrict__ edge, const float* __restrict__ seg,
                  const float* __restrict__ pe,   const float* __restrict__ ps) {
    int b = blockIdx.z;
    int c = blockIdx.y;
    int p0 = blockIdx.x * 2048 + threadIdx.x * 8;
    half* dst = g_auxh + ((long)b * AUXK + c) * HW + p0;
    half h[8];
    if (c < AUXC) {
        const float* src;
        if (c < 128)       src = edge + ((long)b * 128 + c) * HW;
        else if (c < 256)  src = seg  + ((long)b * 128 + (c - 128)) * HW;
        else if (c == 256) src = pe   + (long)b * HW;
        else               src = ps   + ((long)b * 20 + (c - 257)) * HW;
        float4 v0 = *(const float4*)(src + p0);
        float4 v1 = *(const float4*)(src + p0 + 4);
        h[0] = __float2half_rn(v0.x); h[1] = __float2half_rn(v0.y);
        h[2] = __float2half_rn(v0.z); h[3] = __float2half_rn(v0.w);
        h[4] = __float2half_rn(v1.x); h[5] = __float2half_rn(v1.y);
        h[6] = __float2half_rn(v1.z); h[7] = __float2half_rn(v1.w);
    } else {
#pragma unroll
        for (int j = 0; j < 8; j++) h[j] = __ushort_as_half((unsigned short)0);
    }
    *(uint4*)dst = *(uint4*)h;
}

// ================= fp32 -> fp16 convert (vectorized) =================
__global__ void __launch_bounds__(256)
cvt_f2h_kernel(const float* __restrict__ src, half* __restrict__ dst, long n) {
    long i = ((long)blockIdx.x * 256 + threadIdx.x) * 8;
    if (i >= n) return;
    float4 v0 = *(const float4*)(src + i);
    float4 v1 = *(const float4*)(src + i + 4);
    half h[8];
    h[0] = __float2half_rn(v0.x); h[1] = __float2half_rn(v0.y);
    h[2] = __float2half_rn(v0.z); h[3] = __float2half_rn(v0.w);
    h[4] = __float2half_rn(v1.x); h[5] = __float2half_rn(v1.y);
    h[6] = __float2half_rn(v1.z); h[7] = __float2half_rn(v1.w);
    *(uint4*)(dst + i) = *(uint4*)h;
}

// ================= LayerNorm stats =================
__global__ void __launch_bounds__(256)
ln_part_kernel(const float* __restrict__ src) {
    int b = blockIdx.y, ch = blockIdx.x;
    const int CH = CHW / 64;
    const float* p = src + (long)b * CHW + (long)ch * CH;
    int tid = threadIdx.x;
    float s = 0.f, q = 0.f;
    for (int i = tid; i < CH; i += 256) { float v = p[i]; s += v; q += v * v; }
    __shared__ float shs[8], shq[8];
#pragma unroll
    for (int o = 16; o; o >>= 1) {
        s += __shfl_xor_sync(0xffffffffu, s, o);
        q += __shfl_xor_sync(0xffffffffu, q, o);
    }
    if ((tid & 31) == 0) { shs[tid >> 5] = s; shq[tid >> 5] = q; }
    __syncthreads();
    if (tid < 8) {
        s = shs[tid]; q = shq[tid];
#pragma unroll
        for (int o = 4; o; o >>= 1) {
            s += __shfl_xor_sync(0xffu, s, o);
            q += __shfl_xor_sync(0xffu, q, o);
        }
        if (tid == 0) {
            g_part[(b * 64 + ch) * 2 + 0] = s;
            g_part[(b * 64 + ch) * 2 + 1] = q;
        }
    }
}

__global__ void ln_final_kernel() {
    int b = blockIdx.x;
    int tid = threadIdx.x;
    float s = 0.f, q = 0.f;
    for (int i = tid; i < 64; i += 32) {
        s += g_part[(b * 64 + i) * 2 + 0];
        q += g_part[(b * 64 + i) * 2 + 1];
    }
#pragma unroll
    for (int o = 16; o; o >>= 1) {
        s += __shfl_xor_sync(0xffffffffu, s, o);
        q += __shfl_xor_sync(0xffffffffu, q, o);
    }
    if (tid == 0) {
        float mu = s / (float)CHW;
        float var = q / (float)CHW - mu * mu;
        g_stats[2 * b]     = mu;
        g_stats[2 * b + 1] = rsqrtf(var + 1e-5f);
    }
}

// ================= softmax (half in, half out) =================
__global__ void __launch_bounds__(256)
softmax_hh_kernel(const half* __restrict__ S, half* __restrict__ P, int L, int VPT) {
    long row = blockIdx.x;
    const half* p = S + row * (long)L;
    half* o = P + row * (long)L;
    int tid = threadIdx.x;
    __shared__ float sh[8];
    float v[4];
    for (int i = 0; i < VPT; i++) v[i] = __half2float(p[tid + i * 256]);

    float mx = -3.4e38f;
    for (int i = 0; i < VPT; i++) mx = fmaxf(mx, v[i]);
#pragma unroll
    for (int og = 16; og; og >>= 1) mx = fmaxf(mx, __shfl_xor_sync(0xffffffffu, mx, og));
    if ((tid & 31) == 0) sh[tid >> 5] = mx;
    __syncthreads();
    if (tid < 8) {
        float t = sh[tid];
#pragma unroll
        for (int og = 4; og; og >>= 1) t = fmaxf(t, __shfl_xor_sync(0xffu, t, og));
        if (tid == 0) sh[0] = t;
    }
    __syncthreads();
    mx = sh[0];
    __syncthreads();

    float s = 0.f;
    for (int i = 0; i < VPT; i++) { v[i] = __expf(v[i] - mx); s += v[i]; }
#pragma unroll
    for (int og = 16; og; og >>= 1) s += __shfl_xor_sync(0xffffffffu, s, og);
    if ((tid & 31) == 0) sh[tid >> 5] = s;
    __syncthreads();
    if (tid < 8) {
        float t = sh[tid];
#pragma unroll
        for (int og = 4; og; og >>= 1) t += __shfl_xor_sync(0xffu, t, og);
        if (tid == 0) sh[0] = t;
    }
    __syncthreads();
    float inv = 1.f / sh[0];
    for (int i = 0; i < VPT; i++) o[tid + i * 256] = __float2half_rn(v[i] * inv);
}

// ================= host =================
static void rung(bool transb, bool conv, int nT, int mT, int zT, const GP& g) {
    dim3 grid(nT, mT, zT);
    if (conv)        hgemm9<false, true ><<<grid, 256, GSM_BYTES>>>(g);
    else if (transb) hgemm9<true,  false><<<grid, 256, GSM_BYTES>>>(g);
    else             hgemm9<false, false><<<grid, 256, GSM_BYTES>>>(g);
}

extern "C" void kernel_launch(void* const* d_in, const int* in_sizes, int n_in,
                              void* d_out, int out_size) {
    const float* x    = (const float*)d_in[0];
    const float* edge = (const float*)d_in[1];
    const float* seg  = (const float*)d_in[2];
    const float* pe   = (const float*)d_in[3];
    const float* ps   = (const float*)d_in[4];
    const float* q_w  = (const float*)d_in[5];
    const float* q_b  = (const float*)d_in[6];
    const float* k_w  = (const float*)d_in[7];
    const float* k_b  = (const float*)d_in[8];
    const float* v_w  = (const float*)d_in[9];
    const float* v_b  = (const float*)d_in[10];
    const float* d1_embed_w = (const float*)d_in[11];
    const float* d1_embed_b = (const float*)d_in[12];
    const float* d1_scale_w = (const float*)d_in[13];
    const float* d1_scale_b = (const float*)d_in[14];
    const float* d1_bias_w  = (const float*)d_in[15];
    const float* d1_bias_b  = (const float*)d_in[16];
    const float* d2_embed_w = (const float*)d_in[17];
    const float* d2_embed_b = (const float*)d_in[18];
    const float* d2_scale_w = (const float*)d_in[19];
    const float* d2_scale_b = (const float*)d_in[20];
    const float* d2_bias_w  = (const float*)d_in[21];
    const float* d2_bias_b  = (const float*)d_in[22];
    const float* sc_w  = (const float*)d_in[23];
    const float* sc_b  = (const float*)d_in[24];
    const float* bi1_w = (const float*)d_in[25];
    const float* bi1_b = (const float*)d_in[26];
    const float* bi2_w = (const float*)d_in[27];
    const float* bi2_b = (const float*)d_in[28];
    float* out = (float*)d_out;

    cudaFuncSetAttribute(hgemm9<false, false>, cudaFuncAttributeMaxDynamicSharedMemorySize, GSM_BYTES);
    cudaFuncSetAttribute(hgemm9<true,  false>, cudaFuncAttributeMaxDynamicSharedMemorySize, GSM_BYTES);
    cudaFuncSetAttribute(hgemm9<false, true >, cudaFuncAttributeMaxDynamicSharedMemorySize, GSM_BYTES);

    half *wh, *auxh, *xh, *ah, *t0h, *midh, *oh, *tmph;
    half *qp1, *kp1, *vp1, *qp2, *kp2, *vp2, *s1h, *s2h;
    float *t0f, *gam, *bet, *midf, *gf, *stats;
    float *qkvb, *gbb1, *gbb2;
    cudaGetSymbolAddress((void**)&wh,   g_wh);
    cudaGetSymbolAddress((void**)&auxh, g_auxh);
    cudaGetSymbolAddress((void**)&xh,   g_xh);
    cudaGetSymbolAddress((void**)&ah,   g_ah);
    cudaGetSymbolAddress((void**)&t0h,  g_t0h);
    cudaGetSymbolAddress((void**)&t0f,  g_t0f);
    cudaGetSymbolAddress((void**)&gam,  g_gam);
    cudaGetSymbolAddress((void**)&bet,  g_bet);
    cudaGetSymbolAddress((void**)&midh, g_midh);
    cudaGetSymbolAddress((void**)&midf, g_midf);
    cudaGetSymbolAddress((void**)&oh,   g_oh);
    cudaGetSymbolAddress((void**)&gf,   g_gf);
    cudaGetSymbolAddress((void**)&tmph, g_tmph);
    cudaGetSymbolAddress((void**)&qp1,  g_qp1);
    cudaGetSymbolAddress((void**)&kp1,  g_kp1);
    cudaGetSymbolAddress((void**)&vp1,  g_vp1);
    cudaGetSymbolAddress((void**)&qp2,  g_qp2);
    cudaGetSymbolAddress((void**)&kp2,  g_kp2);
    cudaGetSymbolAddress((void**)&vp2,  g_vp2);
    cudaGetSymbolAddress((void**)&s1h,  g_s1h);
    cudaGetSymbolAddress((void**)&s2h,  g_s2h);
    cudaGetSymbolAddress((void**)&stats, g_stats);
    cudaGetSymbolAddress((void**)&qkvb, g_qkvb);
    cudaGetSymbolAddress((void**)&gbb1, g_gbb1);
    cudaGetSymbolAddress((void**)&gbb2, g_gbb2);

    // 0. conversions / packing
    wconv_kernel<<<(W_TOTAL + 255) / 256, 256>>>(q_w, k_w, v_w,
                                                 d1_embed_w, d1_scale_w, d1_bias_w,
                                                 d2_embed_w, d2_scale_w, d2_bias_w,
                                                 sc_w, bi1_w, bi2_w);
    biaspack_kernel<<<4, 256>>>(q_b, k_b, v_b, d1_scale_b, d1_bias_b, d2_scale_b, d2_bias_b);
    cvt_f2h_kernel<<<(int)(((long)NB * CHW / 8 + 255) / 256), 256>>>(x, xh, (long)NB * CHW);
    concat_aux_kernel<<<dim3(2, AUXK, NB), 256>>>(edge, seg, pe, ps);

    // 1. ADN-1 shared: a = E1(aux); gamma/betaS = GB1(a)
    {
        GP p = {};
        p.A = wh + WO_E1; p.lda = AUXK; p.sA = 0;
        p.B = auxh; p.ldb = HW; p.sB = (long)AUXK * HW;
        p.N = HW; p.sC = CHW; p.nkt = AUXK / 64; p.mode = EP_LIN;
        p.bias = d1_embed_b; p.ohh = ah;
        rung(false, false, 32, 1, NB, p);
    }
    {
        GP p = {};
        p.A = wh + WO_GB1; p.lda = 128; p.sA = 0;
        p.B = ah; p.ldb = HW; p.sB = CHW;
        p.N = HW; p.sC = CHW; p.nkt = 2; p.mode = EP_GB;
        p.bias = gbb1; p.of = gam; p.of2 = bet;
        rung(false, false, 32, 2, NB, p);
    }

    // 2. q/k/v conv1x1 merged (M=384)
    {
        GP p = {};
        p.A = wh + WO_QKV; p.lda = 128; p.sA = 0;
        p.B = xh; p.ldb = HW; p.sB = CHW;
        p.N = HW; p.sC = 3L * CHW; p.nkt = 2; p.mode = EP_LIN;
        p.bias = qkvb; p.of = t0f; p.ohh = t0h;
        rung(false, false, 32, 3, NB, p);
    }
    ln_part_kernel<<<dim3(64, 48), 256>>>(t0f);
    ln_final_kernel<<<48, 32>>>();

    // 3. ADN-apply merged (48 batches), fused patched writes
    {
        GP p = {};
        p.A = wh + WO_B1; p.lda = 256; p.sA = 0;
        p.B = t0h; p.ldb = HW; p.sB = CHW;
        p.N = HW; p.sC = CHW; p.nkt = 2; p.mode = EP_QKV3;
        p.t0f = t0f; p.gamma = gam; p.betaS = bet; p.stats = stats;
        p.d1q = qp1; p.d1k = kp1; p.d1v = vp1;
        p.d2q = qp2; p.d2k = kp2; p.d2v = vp2;
        rung(false, false, 32, 1, 48, p);
    }

    // 4. attention scale 1
    {
        GP p = {};
        p.A = qp1; p.lda = 256; p.sA = 1024L * 256;
        p.B = kp1; p.ldb = 256; p.sB = 1024L * 256;
        p.N = 1024; p.sC = 1024L * 1024; p.nkt = 4; p.mode = EP_SCORE; p.scale = 0.0625f;
        p.ohh = s1h;
        rung(true, false, 8, 8, NB, p);
    }
    softmax_hh_kernel<<<NB * 1024, 256>>>(s1h, s1h, 1024, 4);
    {
        GP p = {};
        p.A = s1h; p.lda = 1024; p.sA = 1024L * 1024;
        p.B = vp1; p.ldb = 256; p.sB = 1024L * 256;
        p.N = 256; p.sC = CHW; p.nkt = 16; p.mode = EP_PV1;
        p.xres = x; p.of = midf; p.ohh = midh;
        rung(false, false, 2, 8, NB, p);
    }

    // 5. attention scale 2
    {
        GP p = {};
        p.A = qp2; p.lda = 1024; p.sA = 256L * 1024;
        p.B = kp2; p.ldb = 1024; p.sB = 256L * 1024;
        p.N = 256; p.sC = 256L * 256; p.nkt = 16; p.mode = EP_SCORE; p.scale = 0.03125f;
        p.ohh = s2h;
        rung(true, false, 2, 2, NB, p);
    }
    softmax_hh_kernel<<<NB * 256, 256>>>(s2h, s2h, 256, 1);
    {
        GP p = {};
        p.A = s2h; p.lda = 256; p.sA = 256L * 256;
        p.B = vp2; p.ldb = 1024; p.sB = 256L * 1024;
        p.N = 1024; p.sC = CHW; p.nkt = 4; p.mode = EP_PV2;
        p.xres = x; p.of = midf; p.ohh = midh;
        rung(false, false, 8, 2, NB, p);
    }

    // 6. ADN-2
    {
        GP p = {};
        p.A = wh + WO_E2; p.lda = AUXK; p.sA = 0;
        p.B = auxh; p.ldb = HW; p.sB = (long)AUXK * HW;
        p.N = HW; p.sC = CHW; p.nkt = AUXK / 64; p.mode = EP_LIN;
        p.bias = d2_embed_b; p.ohh = ah;
        rung(false, false, 32, 1, NB, p);
    }
    {
        GP p = {};
        p.A = wh + WO_GB2; p.lda = 128; p.sA = 0;
        p.B = ah; p.ldb = HW; p.sB = CHW;
        p.N = HW; p.sC = CHW; p.nkt = 2; p.mode = EP_GB;
        p.bias = gbb2; p.of = gam; p.of2 = bet;
        rung(false, false, 32, 2, NB, p);
    }
    ln_part_kernel<<<dim3(64, NB), 256>>>(midf);
    ln_final_kernel<<<NB, 32>>>();
    {
        GP p = {};
        p.A = wh + WO_B2; p.lda = 256; p.sA = 0;
        p.B = midh; p.ldb = HW; p.sB = CHW;
        p.N = HW; p.sC = CHW; p.nkt = 2; p.mode = EP_ADN;
        p.t0f = midf; p.gamma = gam; p.betaS = bet; p.stats = stats;
        p.ohh = oh;
        rung(false, false, 32, 1, NB, p);
    }

    // 7. conv3x3 chain (coalesced plane-major gather, K=1152)
    {
        GP p = {};
        p.A = wh + WO_SC; p.lda = 1152; p.sA = 0;
        p.B = oh; p.ldb = 0; p.sB = CHW;
        p.N = HW; p.sC = CHW; p.nkt = 18; p.mode = EP_TANH; p.dil = 1;
        p.bias = sc_b; p.of = gf;
        rung(false, true, 32, 1, NB, p);
    }
    {
        GP p = {};
        p.A = wh + WO_BI1; p.lda = 1152; p.sA = 0;
        p.B = oh; p.ldb = 0; p.sB = CHW;
        p.N = HW; p.sC = CHW; p.nkt = 18; p.mode = EP_GELU; p.dil = 2;
        p.bias = bi1_b; p.ohh = tmph;
        rung(false, true, 32, 1, NB, p);
    }
    {
        GP p = {};
        p.A = wh + WO_BI2; p.lda = 1152; p.sA = 0;
        p.B = tmph; p.ldb = 0; p.sB = CHW;
        p.N = HW; p.sC = CHW; p.nkt = 18; p.mode = EP_FINAL; p.dil = 1;
        p.bias = bi2_b; p.midf = midf; p.gff = gf; p.of = out;
        rung(false, true, 32, 1, NB, p);
    }
}

// round 10
// speedup vs baseline: 1.4705x; 1.0538x over previous
#include <cuda_runtime.h>
#include <cuda_fp16.h>
#include <math.h>
#include <stdint.h>

// ---------------- problem constants ----------------
#define NB 16
#define HW 4096
#define CHW (128*HW)          // 524288
#define AUXC 277
#define AUXK 320

// ---------------- weight pack offsets (halfs) ----------------
#define WO_QKV  0             // [384][128]
#define WO_E1   49152         // [128][320]
#define WO_GB1  90112         // [256][128]
#define WO_B1   122880        // [128][256]
#define WO_E2   155648
#define WO_GB2  196608
#define WO_B2   229376
#define WO_SC   262144        // [128][1152] plane-major
#define WO_BI1  409600
#define WO_BI2  557056
#define W_TOTAL 704512

// ---------------- scratch ----------------
__device__ __align__(256) half  g_wh  [W_TOTAL];
__device__ float g_qkvb[384];
__device__ float g_gbb1[256];
__device__ float g_gbb2[256];
__device__ __align__(256) half  g_auxh[(long)NB*AUXK*HW];
__device__ __align__(256) half  g_xh  [(long)NB*CHW];
__device__ __align__(256) half  g_ah  [(long)NB*CHW];
__device__ __align__(256) half  g_t0h [(long)NB*3*CHW];
__device__ __align__(256) half  g_gamh[(long)NB*CHW];
__device__ __align__(256) half  g_beth[(long)NB*CHW];
__device__ __align__(256) half  g_midh[(long)NB*CHW];
__device__ __align__(256) half  g_oh  [(long)NB*CHW];
__device__ __align__(256) half  g_gfh [(long)NB*CHW];
__device__ __align__(256) half  g_tmph[(long)NB*CHW];
__device__ __align__(256) half  g_qp1 [NB*1024L*256];
__device__ __align__(256) half  g_kp1 [NB*1024L*256];
__device__ __align__(256) half  g_vp1 [NB*1024L*256];
__device__ __align__(256) half  g_qp2 [NB*256L*1024];
__device__ __align__(256) half  g_kp2 [NB*256L*1024];
__device__ __align__(256) half  g_vp2 [NB*256L*1024];
__device__ __align__(256) half  g_s1h [NB*1024L*1024];
__device__ __align__(256) half  g_s2h [NB*256L*256];
__device__ float g_stats[96];
__device__ float g_acc  [96];   // (sum, sumsq) per LN group

// ---------------- epilogue modes ----------------
#define EP_LIN   0
#define EP_GB    1
#define EP_QKV3  2
#define EP_ADN   3
#define EP_SCORE 4
#define EP_PV1   5
#define EP_PV2   6
#define EP_TANH  7
#define EP_GELU  8
#define EP_FINAL 9

// ---------------- smem geometry (halfs), Kt = 64 ----------------
#define A_LDH 72
#define A_ROWB 144
#define BK_LDH 136
#define BK_ROWB 272
#define STAGE_HALFS 18432
#define STAGE_BYTES 36864
#define B_OFF_H 9216
#define GSM_BYTES (2*STAGE_BYTES)

// ---------------- asm helpers ----------------
__device__ __forceinline__ uint32_t smem_u32(const void* p) {
    uint32_t a;
    asm("{ .reg .u64 t; cvta.to.shared.u64 t, %1; cvt.u32.u64 %0, t; }" : "=r"(a) : "l"(p));
    return a;
}
__device__ __forceinline__ void ldsm_x4(uint32_t* r, uint32_t addr) {
    asm volatile("ldmatrix.sync.aligned.m8n8.x4.shared.b16 {%0,%1,%2,%3}, [%4];"
                 : "=r"(r[0]), "=r"(r[1]), "=r"(r[2]), "=r"(r[3]) : "r"(addr));
}
__device__ __forceinline__ void ldsm_x4t(uint32_t* r, uint32_t addr) {
    asm volatile("ldmatrix.sync.aligned.m8n8.x4.trans.shared.b16 {%0,%1,%2,%3}, [%4];"
                 : "=r"(r[0]), "=r"(r[1]), "=r"(r[2]), "=r"(r[3]) : "r"(addr));
}
__device__ __forceinline__ void mma_f16(float* c,
                                        uint32_t a0, uint32_t a1, uint32_t a2, uint32_t a3,
                                        uint32_t b0, uint32_t b1) {
    asm volatile(
        "mma.sync.aligned.m16n8k16.row.col.f32.f16.f16.f32 "
        "{%0,%1,%2,%3}, {%4,%5,%6,%7}, {%8,%9}, {%0,%1,%2,%3};"
        : "+f"(c[0]), "+f"(c[1]), "+f"(c[2]), "+f"(c[3])
        : "r"(a0), "r"(a1), "r"(a2), "r"(a3), "r"(b0), "r"(b1));
}

// ---------------- GEMM params ----------------
struct GP {
    const half* A; int lda; long sA;
    const half* B; int ldb; long sB;
    int N; long sC; int nkt;
    int mode; float scale; int dil; int lng;   // lng: 0 none, 1 group=bb*3+m0/128, 2 group=bb
    const float* bias;
    const half* t0h; const half* gamh; const half* beth; const float* stats;
    const float* xres; const half* midh; const half* gfh;
    float* of; half* ohh; half* ohh2;
    half* d1q; half* d1k; half* d1v;
    half* d2q; half* d2k; half* d2v;
    float* acc;
};

// ================= fp16 tensor-core GEMM, Kt=64 =================
template<bool TRANSB, bool CONV>
__global__ void __launch_bounds__(256)
hgemm10(GP g) {
    extern __shared__ __align__(16) half sm[];
    int bb = blockIdx.z;
    int n0 = blockIdx.x * 128;
    int m0 = blockIdx.y * 128;
    const half* Ap = g.A + (long)bb * g.sA;
    const half* Bp = g.B + (long)bb * g.sB;

    int tid  = threadIdx.x;
    int lane = tid & 31;
    int warp = tid >> 5;
    int wm = (warp >> 2) * 64;
    int wn = (warp & 3) * 32;

    int arow  = tid >> 1;
    int akseg = (tid & 1) * 32;
    int bkr = tid >> 2;
    int bns = (tid & 3) * 32;
    int cn    = tid & 127;
    int ckseg = (tid >> 7) * 32;

    uint32_t sbase = smem_u32(sm);
    int rowsel = lane & 15;
    int colsel = (lane >> 4) * 16;

    uint4 ra[4], rb[4];
    float acc[4][4][4] = {};
    int nkt = g.nkt;

    for (int it = 0; it <= nkt; it++) {
        if (it < nkt) {
            int kt = it * 64;
            const half* ar = Ap + (long)(m0 + arow) * g.lda + kt + akseg;
#pragma unroll
            for (int j = 0; j < 4; j++) ra[j] = *(const uint4*)(ar + j * 8);
            if (CONV) {
                int tap = kt >> 7;
                int cb  = (kt & 127) + ckseg;
                int dy = (tap / 3 - 1) * g.dil;
                int dx = (tap % 3 - 1) * g.dil;
                int p = n0 + cn;
                int h = (p >> 6) + dy;
                int w = (p & 63) + dx;
                half rc[32];
                if ((unsigned)h < 64u && (unsigned)w < 64u) {
                    const half* base = Bp + (long)cb * HW + h * 64 + w;
#pragma unroll
                    for (int j = 0; j < 32; j++) rc[j] = base[(long)j * HW];
                } else {
#pragma unroll
                    for (int j = 0; j < 32; j++) rc[j] = __ushort_as_half((unsigned short)0);
                }
#pragma unroll
                for (int j = 0; j < 4; j++) rb[j] = ((uint4*)rc)[j];
            } else if (TRANSB) {
                const half* br = Bp + (long)(n0 + arow) * g.ldb + kt + akseg;
#pragma unroll
                for (int j = 0; j < 4; j++) rb[j] = *(const uint4*)(br + j * 8);
            } else {
                const half* br = Bp + (long)(kt + bkr) * g.ldb + n0 + bns;
#pragma unroll
                for (int j = 0; j < 4; j++) rb[j] = *(const uint4*)(br + j * 8);
            }
        }

        if (it > 0) {
            uint32_t stA = sbase + (uint32_t)(((it - 1) & 1) * STAGE_BYTES);
            uint32_t stB = stA + B_OFF_H * 2;
            uint32_t abase = stA + (uint32_t)(wm + rowsel) * A_ROWB + colsel;
#pragma unroll
            for (int ks = 0; ks < 4; ks++) {
                uint32_t af[4][4];
#pragma unroll
                for (int mt = 0; mt < 4; mt++)
                    ldsm_x4(af[mt], abase + mt * 16 * A_ROWB + ks * 32);
                uint32_t bf[2][4];
                if (TRANSB || CONV) {
                    uint32_t bbase = stB + (uint32_t)(wn + rowsel) * A_ROWB + colsel;
#pragma unroll
                    for (int ntp = 0; ntp < 2; ntp++)
                        ldsm_x4(bf[ntp], bbase + ntp * 16 * A_ROWB + ks * 32);
                } else {
                    uint32_t bbase = stB + (uint32_t)(ks * 16 + rowsel) * BK_ROWB
                                   + (uint32_t)(wn + (lane >> 4) * 8) * 2;
#pragma unroll
                    for (int ntp = 0; ntp < 2; ntp++)
                        ldsm_x4t(bf[ntp], bbase + ntp * 32);
                }
#pragma unroll
                for (int mt = 0; mt < 4; mt++) {
#pragma unroll
                    for (int nt = 0; nt < 4; nt++) {
                        int ntp = nt >> 1, par = nt & 1;
                        uint32_t b0, b1;
                        if (TRANSB || CONV) { b0 = bf[ntp][par];     b1 = bf[ntp][par + 2]; }
                        else                { b0 = bf[ntp][par * 2]; b1 = bf[ntp][par * 2 + 1]; }
                        mma_f16(acc[mt][nt],
                                af[mt][0], af[mt][1], af[mt][2], af[mt][3], b0, b1);
                    }
                }
            }
        }

        if (it < nkt) {
            half* stA = sm + (it & 1) * STAGE_HALFS;
            half* stB = stA + B_OFF_H;
            half* da = stA + arow * A_LDH + akseg;
#pragma unroll
            for (int j = 0; j < 4; j++) *(uint4*)(da + j * 8) = ra[j];
            half* db;
            if (CONV)        db = stB + cn * A_LDH + ckseg;
            else if (TRANSB) db = stB + arow * A_LDH + akseg;
            else             db = stB + bkr * BK_LDH + bns;
#pragma unroll
            for (int j = 0; j < 4; j++) *(uint4*)(db + j * 8) = rb[j];
        }
        __syncthreads();
    }

    // ---- epilogue ----
    int r  = lane >> 2;
    int cg = lane & 3;
    int mode = g.mode;
    int N = g.N;
    long bbC = (long)bb * g.sC;
    float mu = 0.f, rs = 0.f;
    if (mode == EP_QKV3 || mode == EP_ADN) { mu = g.stats[2 * bb]; rs = g.stats[2 * bb + 1]; }
    int b3 = bb / 3, t3 = bb - 3 * (bb / 3);
    float lsum = 0.f, lsq = 0.f;

    auto emit = [&](float v, int m, int n) {
        long li = (long)m * N + n;
        if (mode == EP_LIN) {
            float res = v + g.bias[m];
            if (g.lng) { lsum += res; lsq += res * res; }
            g.ohh[bbC + li] = __float2half_rn(res);
        } else if (mode == EP_GB) {
            float res = v + g.bias[m];
            long o = (long)bb * CHW + (long)(m & 127) * HW + n;
            if (m < 128) g.ohh [o] = __float2half_rn(res);
            else         g.ohh2[o] = __float2half_rn(res);
        } else if (mode == EP_QKV3) {
            long ti = bbC + li;
            long gi = (long)b3 * CHW + li;
            float val = (__half2float(g.t0h[ti]) - mu) * rs * __half2float(g.gamh[gi])
                        + v + __half2float(g.beth[gi]);
            half hv = __float2half_rn(val);
            int h = n >> 6, w = n & 63;
            if (m < 64) {
                int tk = (h >> 1) * 32 + (w >> 1);
                int d  = m * 4 + (h & 1) * 2 + (w & 1);
                half* dst = (t3 == 0) ? g.d1q : (t3 == 1) ? g.d1k : g.d1v;
                dst[(long)b3 * (1024L * 256) + (long)tk * 256 + d] = hv;
            } else {
                int tk = (h >> 2) * 16 + (w >> 2);
                int d  = (m - 64) * 16 + (h & 3) * 4 + (w & 3);
                half* dst = (t3 == 0) ? g.d2q : (t3 == 1) ? g.d2k : g.d2v;
                dst[(long)b3 * (256L * 1024) + (long)tk * 1024 + d] = hv;
            }
        } else if (mode == EP_ADN) {
            long gi = bbC + li;
            float res = (__half2float(g.t0h[gi]) - mu) * rs * __half2float(g.gamh[gi])
                        + v + __half2float(g.beth[gi]);
            g.ohh[gi] = __float2half_rn(res);
        } else if (mode == EP_SCORE) {
            g.ohh[bbC + li] = __float2half_rn(v * g.scale);
        } else if (mode == EP_PV1) {
            int c  = n >> 2;
            int py = (n >> 1) & 1, px = n & 1;
            int h = (m >> 5) * 2 + py, w = (m & 31) * 2 + px;
            long tgt = bbC + (long)c * HW + h * 64 + w;
            float res = g.xres[tgt] + v;
            lsum += res; lsq += res * res;
            g.ohh[tgt] = __float2half_rn(res);
        } else if (mode == EP_PV2) {
            int c  = 64 + (n >> 4);
            int py = (n >> 2) & 3, px = n & 3;
            int h = (m >> 4) * 4 + py, w = (m & 15) * 4 + px;
            long tgt = bbC + (long)c * HW + h * 64 + w;
            float res = g.xres[tgt] + v;
            lsum += res; lsq += res * res;
            g.ohh[tgt] = __float2half_rn(res);
        } else if (mode == EP_TANH) {
            g.ohh[bbC + li] = __float2half_rn(tanhf(v + g.bias[m]));
        } else if (mode == EP_GELU) {
            float u = v + g.bias[m];
            g.ohh[bbC + li] = __float2half_rn(0.5f * u * (1.f + erff(u * 0.70710678118654752f)));
        } else { // EP_FINAL
            long gi = bbC + li;
            g.of[gi] = __half2float(g.midh[gi]) * __half2float(g.gfh[gi]) + v + g.bias[m];
        }
    };

#pragma unroll
    for (int mt = 0; mt < 4; mt++) {
#pragma unroll
        for (int nt = 0; nt < 4; nt++) {
            int m1 = m0 + wm + mt * 16 + r;
            int m2 = m1 + 8;
            int nn = n0 + wn + nt * 8 + cg * 2;
            emit(acc[mt][nt][0], m1, nn);
            emit(acc[mt][nt][1], m1, nn + 1);
            emit(acc[mt][nt][2], m2, nn);
            emit(acc[mt][nt][3], m2, nn + 1);
        }
    }

    // ---- fused LN partial-stats reduction ----
    if (g.lng) {
#pragma unroll
        for (int o = 16; o; o >>= 1) {
            lsum += __shfl_xor_sync(0xffffffffu, lsum, o);
            lsq  += __shfl_xor_sync(0xffffffffu, lsq,  o);
        }
        float* smf = (float*)sm;
        if (lane == 0) { smf[warp * 2] = lsum; smf[warp * 2 + 1] = lsq; }
        __syncthreads();
        if (warp == 0 && lane < 8) {
            lsum = smf[lane * 2]; lsq = smf[lane * 2 + 1];
#pragma unroll
            for (int o = 4; o; o >>= 1) {
                lsum += __shfl_xor_sync(0xffu, lsum, o);
                lsq  += __shfl_xor_sync(0xffu, lsq,  o);
            }
            if (lane == 0) {
                int grp = (g.lng == 1) ? bb * 3 + (m0 >> 7) : bb;
                atomicAdd(&g.acc[2 * grp],     lsum);
                atomicAdd(&g.acc[2 * grp + 1], lsq);
            }
        }
    }
}

// ================= weight repack =================
__global__ void __launch_bounds__(256)
wconv_kernel(const float* qw, const float* kw, const float* vw,
             const float* e1, const float* s1, const float* b1,
             const float* e2, const float* s2, const float* b2,
             const float* sc, const float* bi1, const float* bi2) {
    int i = blockIdx.x * 256 + threadIdx.x;
    if (i >= W_TOTAL) return;
    float v;
    if (i < WO_E1) {
        int t = i >> 14, j = i & 16383;
        v = (t == 0 ? qw : t == 1 ? kw : vw)[j];
    } else if (i < WO_GB1) {
        int j = i - WO_E1, r = j / AUXK, c = j % AUXK;
        v = (c < AUXC) ? e1[r * AUXC + c] : 0.f;
    } else if (i < WO_B1) {
        int j = i - WO_GB1, r = j >> 7, c = j & 127;
        v = (r < 128) ? s1[r * 128 + c] : b1[(r - 128) * 256 + 128 + c];
    } else if (i < WO_E2) {
        v = b1[i - WO_B1];
    } else if (i < WO_GB2) {
        int j = i - WO_E2, r = j / AUXK, c = j % AUXK;
        v = (c < AUXC) ? e2[r * AUXC + c] : 0.f;
    } else if (i < WO_B2) {
        int j = i - WO_GB2, r = j >> 7, c = j & 127;
        v = (r < 128) ? s2[r * 128 + c] : b2[(r - 128) * 256 + 128 + c];
    } else if (i < WO_SC) {
        v = b2[i - WO_B2];
    } else {
        int j = i - WO_SC;
        int blk = j / 147456, t = j % 147456;
        int o = t / 1152, rr = t % 1152;
        int tap = rr >> 7, c = rr & 127;
        const float* w = (blk == 0 ? sc : blk == 1 ? bi1 : bi2);
        v = w[((o * 128 + c) * 3 + tap / 3) * 3 + (tap % 3)];
    }
    g_wh[i] = __float2half_rn(v);
}

__global__ void __launch_bounds__(256)
biaspack_kernel(const float* qb, const float* kb, const float* vb,
                const float* s1b, const float* b1b,
                const float* s2b, const float* b2b) {
    int i = blockIdx.x * 256 + threadIdx.x;
    if (i < 384) {
        g_qkvb[i] = i < 128 ? qb[i] : i < 256 ? kb[i - 128] : vb[i - 256];
    } else if (i < 640) {
        int j = i - 384;
        g_gbb1[j] = j < 128 ? s1b[j] : b1b[j - 128];
    } else if (i < 896) {
        int j = i - 640;
        g_gbb2[j] = j < 128 ? s2b[j] : b2b[j - 128];
    }
}

// ================= concat aux =================
__global__ void __launch_bounds__(256)
concat_aux_kernel(const float* __restrict__ edge, const float* __restrict__ seg,
                  const float* __restrict__ pe,   const float* __restrict__ ps) {
    int b = blockIdx.z;
    int c = blockIdx.y;
    int p0 = blockIdx.x * 2048 + threadIdx.x * 8;
    half* dst = g_auxh + ((long)b * AUXK + c) * HW + p0;
    half h[8];
    if (c < AUXC) {
        const float* src;
        if (c < 128)       src = edge + ((long)b * 128 + c) * HW;
        else if (c < 256)  src = seg  + ((long)b * 128 + (c - 128)) * HW;
        else if (c == 256) src = pe   + (long)b * HW;
        else               src = ps   + ((long)b * 20 + (c - 257)) * HW;
        float4 v0 = *(const float4*)(src + p0);
        float4 v1 = *(const float4*)(src + p0 + 4);
        h[0] = __float2half_rn(v0.x); h[1] = __float2half_rn(v0.y);
        h[2] = __float2half_rn(v0.z); h[3] = __float2half_rn(v0.w);
        h[4] = __float2half_rn(v1.x); h[5] = __float2half_rn(v1.y);
        h[6] = __float2half_rn(v1.z); h[7] = __float2half_rn(v1.w);
    } else {
#pragma unroll
        for (int j = 0; j < 8; j++) h[j] = __ushort_as_half((unsigned short)0);
    }
    *(uint4*)dst = *(uint4*)h;
}

__global__ void __launch_bounds__(256)
cvt_f2h_kernel(const float* __restrict__ src, half* __restrict__ dst, long n) {
    long i = ((long)blockIdx.x * 256 + threadIdx.x) * 8;
    if (i >= n) return;
    float4 v0 = *(const float4*)(src + i);
    float4 v1 = *(const float4*)(src + i + 4);
    half h[8];
    h[0] = __float2half_rn(v0.x); h[1] = __float2half_rn(v0.y);
    h[2] = __float2half_rn(v0.z); h[3] = __float2half_rn(v0.w);
    h[4] = __float2half_rn(v1.x); h[5] = __float2half_rn(v1.y);
    h[6] = __float2half_rn(v1.z); h[7] = __float2half_rn(v1.w);
    *(uint4*)(dst + i) = *(uint4*)h;
}

// ================= LN finalize (from fused accumulators) =================
__global__ void ln_final_kernel() {
    int b = blockIdx.x;
    if (threadIdx.x == 0) {
        float s = g_acc[2 * b], q = g_acc[2 * b + 1];
        float mu = s / (float)CHW;
        float var = q / (float)CHW - mu * mu;
        g_stats[2 * b]     = mu;
        g_stats[2 * b + 1] = rsqrtf(var + 1e-5f);
    }
}

// ================= softmax (half in, half out) =================
__global__ void __launch_bounds__(256)
softmax_hh_kernel(const half* __restrict__ S, half* __restrict__ P, int L, int VPT) {
    long row = blockIdx.x;
    const half* p = S + row * (long)L;
    half* o = P + row * (long)L;
    int tid = threadIdx.x;
    __shared__ float sh[8];
    float v[4];
    for (int i = 0; i < VPT; i++) v[i] = __half2float(p[tid + i * 256]);

    float mx = -3.4e38f;
    for (int i = 0; i < VPT; i++) mx = fmaxf(mx, v[i]);
#pragma unroll
    for (int og = 16; og; og >>= 1) mx = fmaxf(mx, __shfl_xor_sync(0xffffffffu, mx, og));
    if ((tid & 31) == 0) sh[tid >> 5] = mx;
    __syncthreads();
    if (tid < 8) {
        float t = sh[tid];
#pragma unroll
        for (int og = 4; og; og >>= 1) t = fmaxf(t, __shfl_xor_sync(0xffu, t, og));
        if (tid == 0) sh[0] = t;
    }
    __syncthreads();
    mx = sh[0];
    __syncthreads();

    float s = 0.f;
    for (int i = 0; i < VPT; i++) { v[i] = __expf(v[i] - mx); s += v[i]; }
#pragma unroll
    for (int og = 16; og; og >>= 1) s += __shfl_xor_sync(0xffffffffu, s, og);
    if ((tid & 31) == 0) sh[tid >> 5] = s;
    __syncthreads();
    if (tid < 8) {
        float t = sh[tid];
#pragma unroll
        for (int og = 4; og; og >>= 1) t += __shfl_xor_sync(0xffu, t, og);
        if (tid == 0) sh[0] = t;
    }
    __syncthreads();
    float inv = 1.f / sh[0];
    for (int i = 0; i < VPT; i++) o[tid + i * 256] = __float2half_rn(v[i] * inv);
}

// ================= host =================
static void rung(bool transb, bool conv, int nT, int mT, int zT, const GP& g) {
    dim3 grid(nT, mT, zT);
    if (conv)        hgemm10<false, true ><<<grid, 256, GSM_BYTES>>>(g);
    else if (transb) hgemm10<true,  false><<<grid, 256, GSM_BYTES>>>(g);
    else             hgemm10<false, false><<<grid, 256, GSM_BYTES>>>(g);
}

extern "C" void kernel_launch(void* const* d_in, const int* in_sizes, int n_in,
                              void* d_out, int out_size) {
    const float* x    = (const float*)d_in[0];
    const float* edge = (const float*)d_in[1];
    const float* seg  = (const float*)d_in[2];
    const float* pe   = (const float*)d_in[3];
    const float* ps   = (const float*)d_in[4];
    const float* q_w  = (const float*)d_in[5];
    const float* q_b  = (const float*)d_in[6];
    const float* k_w  = (const float*)d_in[7];
    const float* k_b  = (const float*)d_in[8];
    const float* v_w  = (const float*)d_in[9];
    const float* v_b  = (const float*)d_in[10];
    const float* d1_embed_w = (const float*)d_in[11];
    const float* d1_embed_b = (const float*)d_in[12];
    const float* d1_scale_w = (const float*)d_in[13];
    const float* d1_scale_b = (const float*)d_in[14];
    const float* d1_bias_w  = (const float*)d_in[15];
    const float* d1_bias_b  = (const float*)d_in[16];
    const float* d2_embed_w = (const float*)d_in[17];
    const float* d2_embed_b = (const float*)d_in[18];
    const float* d2_scale_w = (const float*)d_in[19];
    const float* d2_scale_b = (const float*)d_in[20];
    const float* d2_bias_w  = (const float*)d_in[21];
    const float* d2_bias_b  = (const float*)d_in[22];
    const float* sc_w  = (const float*)d_in[23];
    const float* sc_b  = (const float*)d_in[24];
    const float* bi1_w = (const float*)d_in[25];
    const float* bi1_b = (const float*)d_in[26];
    const float* bi2_w = (const float*)d_in[27];
    const float* bi2_b = (const float*)d_in[28];
    float* out = (float*)d_out;

    cudaFuncSetAttribute(hgemm10<false, false>, cudaFuncAttributeMaxDynamicSharedMemorySize, GSM_BYTES);
    cudaFuncSetAttribute(hgemm10<true,  false>, cudaFuncAttributeMaxDynamicSharedMemorySize, GSM_BYTES);
    cudaFuncSetAttribute(hgemm10<false, true >, cudaFuncAttributeMaxDynamicSharedMemorySize, GSM_BYTES);

    half *wh, *auxh, *xh, *ah, *t0h, *gamh, *beth, *midh, *oh, *gfh, *tmph;
    half *qp1, *kp1, *vp1, *qp2, *kp2, *vp2, *s1h, *s2h;
    float *stats, *acc, *qkvb, *gbb1, *gbb2;
    cudaGetSymbolAddress((void**)&wh,   g_wh);
    cudaGetSymbolAddress((void**)&auxh, g_auxh);
    cudaGetSymbolAddress((void**)&xh,   g_xh);
    cudaGetSymbolAddress((void**)&ah,   g_ah);
    cudaGetSymbolAddress((void**)&t0h,  g_t0h);
    cudaGetSymbolAddress((void**)&gamh, g_gamh);
    cudaGetSymbolAddress((void**)&beth, g_beth);
    cudaGetSymbolAddress((void**)&midh, g_midh);
    cudaGetSymbolAddress((void**)&oh,   g_oh);
    cudaGetSymbolAddress((void**)&gfh,  g_gfh);
    cudaGetSymbolAddress((void**)&tmph, g_tmph);
    cudaGetSymbolAddress((void**)&qp1,  g_qp1);
    cudaGetSymbolAddress((void**)&kp1,  g_kp1);
    cudaGetSymbolAddress((void**)&vp1,  g_vp1);
    cudaGetSymbolAddress((void**)&qp2,  g_qp2);
    cudaGetSymbolAddress((void**)&kp2,  g_kp2);
    cudaGetSymbolAddress((void**)&vp2,  g_vp2);
    cudaGetSymbolAddress((void**)&s1h,  g_s1h);
    cudaGetSymbolAddress((void**)&s2h,  g_s2h);
    cudaGetSymbolAddress((void**)&stats, g_stats);
    cudaGetSymbolAddress((void**)&acc,   g_acc);
    cudaGetSymbolAddress((void**)&qkvb, g_qkvb);
    cudaGetSymbolAddress((void**)&gbb1, g_gbb1);
    cudaGetSymbolAddress((void**)&gbb2, g_gbb2);

    // 0. conversions / packing
    wconv_kernel<<<(W_TOTAL + 255) / 256, 256>>>(q_w, k_w, v_w,
                                                 d1_embed_w, d1_scale_w, d1_bias_w,
                                                 d2_embed_w, d2_scale_w, d2_bias_w,
                                                 sc_w, bi1_w, bi2_w);
    biaspack_kernel<<<4, 256>>>(q_b, k_b, v_b, d1_scale_b, d1_bias_b, d2_scale_b, d2_bias_b);
    cvt_f2h_kernel<<<(int)(((long)NB * CHW / 8 + 255) / 256), 256>>>(x, xh, (long)NB * CHW);
    concat_aux_kernel<<<dim3(2, AUXK, NB), 256>>>(edge, seg, pe, ps);

    // 1. ADN-1 shared
    {
        GP p = {};
        p.A = wh + WO_E1; p.lda = AUXK; p.sA = 0;
        p.B = auxh; p.ldb = HW; p.sB = (long)AUXK * HW;
        p.N = HW; p.sC = CHW; p.nkt = AUXK / 64; p.mode = EP_LIN;
        p.bias = d1_embed_b; p.ohh = ah;
        rung(false, false, 32, 1, NB, p);
    }
    {
        GP p = {};
        p.A = wh + WO_GB1; p.lda = 128; p.sA = 0;
        p.B = ah; p.ldb = HW; p.sB = CHW;
        p.N = HW; p.sC = CHW; p.nkt = 2; p.mode = EP_GB;
        p.bias = gbb1; p.ohh = gamh; p.ohh2 = beth;
        rung(false, false, 32, 2, NB, p);
    }

    // 2. q/k/v conv1x1 merged (M=384), fused LN stats
    cudaMemsetAsync(acc, 0, 96 * sizeof(float));
    {
        GP p = {};
        p.A = wh + WO_QKV; p.lda = 128; p.sA = 0;
        p.B = xh; p.ldb = HW; p.sB = CHW;
        p.N = HW; p.sC = 3L * CHW; p.nkt = 2; p.mode = EP_LIN; p.lng = 1;
        p.bias = qkvb; p.ohh = t0h; p.acc = acc;
        rung(false, false, 32, 3, NB, p);
    }
    ln_final_kernel<<<48, 32>>>();

    // 3. ADN-apply merged (48 z), fused patched writes
    {
        GP p = {};
        p.A = wh + WO_B1; p.lda = 256; p.sA = 0;
        p.B = t0h; p.ldb = HW; p.sB = CHW;
        p.N = HW; p.sC = CHW; p.nkt = 2; p.mode = EP_QKV3;
        p.t0h = t0h; p.gamh = gamh; p.beth = beth; p.stats = stats;
        p.d1q = qp1; p.d1k = kp1; p.d1v = vp1;
        p.d2q = qp2; p.d2k = kp2; p.d2v = vp2;
        rung(false, false, 32, 1, 48, p);
    }

    // 4. attention scale 1
    {
        GP p = {};
        p.A = qp1; p.lda = 256; p.sA = 1024L * 256;
        p.B = kp1; p.ldb = 256; p.sB = 1024L * 256;
        p.N = 1024; p.sC = 1024L * 1024; p.nkt = 4; p.mode = EP_SCORE; p.scale = 0.0625f;
        p.ohh = s1h;
        rung(true, false, 8, 8, NB, p);
    }
    softmax_hh_kernel<<<NB * 1024, 256>>>(s1h, s1h, 1024, 4);
    cudaMemsetAsync(acc, 0, 32 * sizeof(float));
    {
        GP p = {};
        p.A = s1h; p.lda = 1024; p.sA = 1024L * 1024;
        p.B = vp1; p.ldb = 256; p.sB = 1024L * 256;
        p.N = 256; p.sC = CHW; p.nkt = 16; p.mode = EP_PV1; p.lng = 2;
        p.xres = x; p.ohh = midh; p.acc = acc;
        rung(false, false, 2, 8, NB, p);
    }

    // 5. attention scale 2
    {
        GP p = {};
        p.A = qp2; p.lda = 1024; p.sA = 256L * 1024;
        p.B = kp2; p.ldb = 1024; p.sB = 256L * 1024;
        p.N = 256; p.sC = 256L * 256; p.nkt = 16; p.mode = EP_SCORE; p.scale = 0.03125f;
        p.ohh = s2h;
        rung(true, false, 2, 2, NB, p);
    }
    softmax_hh_kernel<<<NB * 256, 256>>>(s2h, s2h, 256, 1);
    {
        GP p = {};
        p.A = s2h; p.lda = 256; p.sA = 256L * 256;
        p.B = vp2; p.ldb = 1024; p.sB = 256L * 1024;
        p.N = 1024; p.sC = CHW; p.nkt = 4; p.mode = EP_PV2; p.lng = 2;
        p.xres = x; p.ohh = midh; p.acc = acc;
        rung(false, false, 8, 2, NB, p);
    }
    ln_final_kernel<<<16, 32>>>();

    // 6. ADN-2
    {
        GP p = {};
        p.A = wh + WO_E2; p.lda = AUXK; p.sA = 0;
        p.B = auxh; p.ldb = HW; p.sB = (long)AUXK * HW;
        p.N = HW; p.sC = CHW; p.nkt = AUXK / 64; p.mode = EP_LIN;
        p.bias = d2_embed_b; p.ohh = ah;
        rung(false, false, 32, 1, NB, p);
    }
    {
        GP p = {};
        p.A = wh + WO_GB2; p.lda = 128; p.sA = 0;
        p.B = ah; p.ldb = HW; p.sB = CHW;
        p.N = HW; p.sC = CHW; p.nkt = 2; p.mode = EP_GB;
        p.bias = gbb2; p.ohh = gamh; p.ohh2 = beth;
        rung(false, false, 32, 2, NB, p);
    }
    {
        GP p = {};
        p.A = wh + WO_B2; p.lda = 256; p.sA = 0;
        p.B = midh; p.ldb = HW; p.sB = CHW;
        p.N = HW; p.sC = CHW; p.nkt = 2; p.mode = EP_ADN;
        p.t0h = midh; p.gamh = gamh; p.beth = beth; p.stats = stats;
        p.ohh = oh;
        rung(false, false, 32, 1, NB, p);
    }

    // 7. conv3x3 chain
    {
        GP p = {};
        p.A = wh + WO_SC; p.lda = 1152; p.sA = 0;
        p.B = oh; p.ldb = 0; p.sB = CHW;
        p.N = HW; p.sC = CHW; p.nkt = 18; p.mode = EP_TANH; p.dil = 1;
        p.bias = sc_b; p.ohh = gfh;
        rung(false, true, 32, 1, NB, p);
    }
    {
        GP p = {};
        p.A = wh + WO_BI1; p.lda = 1152; p.sA = 0;
        p.B = oh; p.ldb = 0; p.sB = CHW;
        p.N = HW; p.sC = CHW; p.nkt = 18; p.mode = EP_GELU; p.dil = 2;
        p.bias = bi1_b; p.ohh = tmph;
        rung(false, true, 32, 1, NB, p);
    }
    {
        GP p = {};
        p.A = wh + WO_BI2; p.lda = 1152; p.sA = 0;
        p.B = tmph; p.ldb = 0; p.sB = CHW;
        p.N = HW; p.sC = CHW; p.nkt = 18; p.mode = EP_FINAL; p.dil = 1;
        p.bias = bi2_b; p.midh = midh; p.gfh = gfh; p.of = out;
        rung(false, true, 32, 1, NB, p);
    }
}